// round 6
// baseline (speedup 1.0000x reference)
#include <cuda_runtime.h>
#include <cuda_bf16.h>
#include <math.h>
#include <stdint.h>

#define NROWS 4096
#define KDIM  1024
#define NHEAD 2002
#define CUT0  2000
#define CUT1  10000
#define NTOK  50257
#define SZ0   8000
#define SZ1   40257
#define D0    256
#define D1    64

// ---------------- scratch (device globals; no allocation allowed) -----------
__device__ float g_proj0[NROWS * D0];
__device__ float g_proj1[NROWS * D1];
__device__ float g_sum_head[NROWS];
__device__ float g_sum_tail[NROWS];
__device__ int   g_idx0[NROWS];
__device__ int   g_idx1[NROWS];
__device__ int   g_cnt0, g_cnt1;

__device__ __align__(16) __nv_bfloat16 g_inh[NROWS * KDIM];
__device__ __align__(16) __nv_bfloat16 g_headWh[NHEAD * KDIM];
__device__ __align__(16) __nv_bfloat16 g_emb0h[SZ0 * D0];
__device__ __align__(16) __nv_bfloat16 g_emb1h[SZ1 * D1];
__device__ __align__(16) __nv_bfloat16 g_proj0h[NROWS * D0];
__device__ __align__(16) __nv_bfloat16 g_proj1h[NROWS * D1];

// ---------------- small helpers ---------------------------------------------
__device__ __forceinline__ void cp16(uint32_t s, const void* g, bool v) {
    if (v) asm volatile("cp.async.cg.shared.global [%0], [%1], 16;\n" :: "r"(s), "l"(g));
    else   asm volatile("cp.async.cg.shared.global [%0], [%1], 16, 0;\n" :: "r"(s), "l"(g));
}
__device__ __forceinline__ void cpcommit() { asm volatile("cp.async.commit_group;\n"); }
template<int N> __device__ __forceinline__ void cpwait() {
    asm volatile("cp.async.wait_group %0;\n" :: "n"(N));
}
__device__ __forceinline__ void mma_bf16(float c[4], const uint32_t a[4], const uint32_t b[2]) {
    asm volatile(
        "mma.sync.aligned.m16n8k16.row.col.f32.bf16.bf16.f32 "
        "{%0,%1,%2,%3}, {%4,%5,%6,%7}, {%8,%9}, {%0,%1,%2,%3};"
        : "+f"(c[0]), "+f"(c[1]), "+f"(c[2]), "+f"(c[3])
        : "r"(a[0]), "r"(a[1]), "r"(a[2]), "r"(a[3]), "r"(b[0]), "r"(b[1]));
}

// ---------------- init / classify / convert ---------------------------------
__global__ void init_kernel() {
    int i = blockIdx.x * blockDim.x + threadIdx.x;
    if (i < NROWS) { g_sum_head[i] = 0.f; g_sum_tail[i] = 0.f; }
    if (i == 0) { g_cnt0 = 0; g_cnt1 = 0; }
}

__global__ void classify_kernel(const int* __restrict__ targets) {
    int i = blockIdx.x * blockDim.x + threadIdx.x;
    if (i >= NROWS) return;
    int t = targets[i];
    if (t >= CUT0 && t < CUT1) { int p = atomicAdd(&g_cnt0, 1); g_idx0[p] = i; }
    else if (t >= CUT1)        { int p = atomicAdd(&g_cnt1, 1); g_idx1[p] = i; }
}

__global__ void cvt_kernel(const float* __restrict__ src, int n, int which) {
    __nv_bfloat16* dst = (which == 0) ? g_inh : (which == 1) ? g_headWh
                       : (which == 2) ? g_emb0h : g_emb1h;
    for (int i = blockIdx.x * blockDim.x + threadIdx.x; i < n; i += gridDim.x * blockDim.x)
        dst[i] = __float2bfloat16(src[i]);
}

// ---------------- projection GEMM (fp32 out + bf16 copy) --------------------
__global__ void __launch_bounds__(256) proj_kernel(
    const float* __restrict__ A, const float* __restrict__ B,
    int K, int dout, int which)
{
    __shared__ float As[64][68];
    __shared__ float Bs[64][68];
    float* __restrict__ P = (which == 0) ? g_proj0 : g_proj1;
    __nv_bfloat16* __restrict__ Ph = (which == 0) ? g_proj0h : g_proj1h;

    int tid = threadIdx.x;
    int tx = tid & 15, ty = tid >> 4;
    int row0 = blockIdx.x * 64;
    int nc   = blockIdx.y * 64;

    float acc[4][4] = {};
    for (int kc = 0; kc < K; kc += 64) {
        __syncthreads();
        {
            int r = tid >> 2, q = tid & 3;
            const float* ga = A + (long)(row0 + r) * K + kc;
            #pragma unroll
            for (int j = 0; j < 4; j++) {
                int c = (q + 4 * j) * 4;
                *reinterpret_cast<float4*>(&As[r][c]) =
                    *reinterpret_cast<const float4*>(ga + c);
            }
        }
        {
            int k = tid >> 2, q = tid & 3;
            const float* gb = B + (long)(kc + k) * dout + nc;
            #pragma unroll
            for (int j = 0; j < 4; j++) {
                int c = (q + 4 * j) * 4;
                *reinterpret_cast<float4*>(&Bs[k][c]) =
                    *reinterpret_cast<const float4*>(gb + c);
            }
        }
        __syncthreads();
        #pragma unroll
        for (int k = 0; k < 64; k++) {
            float4 b = *reinterpret_cast<float4*>(&Bs[k][tx * 4]);
            float a0 = As[ty * 4 + 0][k], a1 = As[ty * 4 + 1][k];
            float a2 = As[ty * 4 + 2][k], a3 = As[ty * 4 + 3][k];
            acc[0][0] += a0 * b.x; acc[0][1] += a0 * b.y; acc[0][2] += a0 * b.z; acc[0][3] += a0 * b.w;
            acc[1][0] += a1 * b.x; acc[1][1] += a1 * b.y; acc[1][2] += a1 * b.z; acc[1][3] += a1 * b.w;
            acc[2][0] += a2 * b.x; acc[2][1] += a2 * b.y; acc[2][2] += a2 * b.z; acc[2][3] += a2 * b.w;
            acc[3][0] += a3 * b.x; acc[3][1] += a3 * b.y; acc[3][2] += a3 * b.z; acc[3][3] += a3 * b.w;
        }
    }
    #pragma unroll
    for (int i = 0; i < 4; i++) {
        long off = (long)(row0 + ty * 4 + i) * dout + nc + tx * 4;
        float4 v = make_float4(acc[i][0], acc[i][1], acc[i][2], acc[i][3]);
        *reinterpret_cast<float4*>(&P[off]) = v;
        __nv_bfloat162 h0 = __floats2bfloat162_rn(v.x, v.y);
        __nv_bfloat162 h1 = __floats2bfloat162_rn(v.z, v.w);
        *reinterpret_cast<__nv_bfloat162*>(&Ph[off])     = h0;
        *reinterpret_cast<__nv_bfloat162*>(&Ph[off + 2]) = h1;
    }
}

// ======================= bf16 tensor-core exp-sum ============================
// Block tile M=256 x N=64, 8 warps as 4m x 2n (warp tile m64 n32).

// ---- HEAD: K=1024, chunked (32) A+B cp.async double buffer ------------------
__global__ void __launch_bounds__(256, 1) expsum_head() {
    extern __shared__ uint32_t sm[];
    const int AST = 20;                   // u32 stride (16 data + 4 pad; 80B = 16B-mult)
    // layout: A[2][256*20] | B[2][64*20] | rowAcc[256]
    float* rowAcc = (float*)(sm + 2 * 5120 + 2 * 1280);

    uint32_t smBase = (uint32_t)__cvta_generic_to_shared(sm);
    uint32_t aBase[2] = { smBase, smBase + 5120u * 4 };
    uint32_t bBase[2] = { smBase + 2u * 5120 * 4, smBase + (2u * 5120 + 1280) * 4 };

    int tid = threadIdx.x;
    rowAcc[tid] = 0.f;
    int row0 = blockIdx.x * 256;
    int warp = tid >> 5, lane = tid & 31, grp = lane >> 2, qid = lane & 3;
    int wm = (warp >> 1) * 64, wn = (warp & 1) * 32;

    const char* aG = (const char*)(g_inh + (size_t)(row0 + tid) * KDIM);
    int bRowLoc = tid >> 2, bSeg = (tid & 3) * 16;

    for (int nc = blockIdx.y * 64; nc < NHEAD; nc += gridDim.y * 64) {
        float c[4][4][4];
        #pragma unroll
        for (int mi = 0; mi < 4; mi++)
            #pragma unroll
            for (int nj = 0; nj < 4; nj++)
                #pragma unroll
                for (int r = 0; r < 4; r++) c[mi][nj][r] = 0.f;

        int bRow = nc + bRowLoc;
        bool bval = bRow < NHEAD;
        const char* bG = (const char*)(g_headWh + (size_t)(bval ? bRow : 0) * KDIM);

        {   // chunk 0
            uint32_t as = aBase[0] + tid * AST * 4;
            #pragma unroll
            for (int s = 0; s < 4; s++) cp16(as + s * 16, aG + s * 16, true);
            cp16(bBase[0] + bRowLoc * AST * 4 + bSeg, bG + bSeg, bval);
            cpcommit();
        }
        const int NCH = KDIM / 32;
        for (int ch = 0; ch < NCH; ch++) {
            int cur = ch & 1;
            if (ch + 1 < NCH) {
                int nb = cur ^ 1;
                uint32_t as = aBase[nb] + tid * AST * 4;
                const char* ag = aG + (ch + 1) * 64;
                #pragma unroll
                for (int s = 0; s < 4; s++) cp16(as + s * 16, ag + s * 16, true);
                cp16(bBase[nb] + bRowLoc * AST * 4 + bSeg, bG + (ch + 1) * 64 + bSeg, bval);
                cpcommit();
                cpwait<1>();
            } else cpwait<0>();
            __syncthreads();
            const uint32_t* Ab = sm + cur * 5120;
            const uint32_t* Bb = sm + 2 * 5120 + cur * 1280;
            #pragma unroll
            for (int ks = 0; ks < 2; ks++) {
                int k0 = ks * 8;
                uint32_t a[4][4], b[4][2];
                #pragma unroll
                for (int mi = 0; mi < 4; mi++) {
                    int r = wm + mi * 16 + grp;
                    a[mi][0] = Ab[r * AST + k0 + qid];
                    a[mi][1] = Ab[(r + 8) * AST + k0 + qid];
                    a[mi][2] = Ab[r * AST + k0 + qid + 4];
                    a[mi][3] = Ab[(r + 8) * AST + k0 + qid + 4];
                }
                #pragma unroll
                for (int nj = 0; nj < 4; nj++) {
                    int n = wn + nj * 8 + grp;
                    b[nj][0] = Bb[n * AST + k0 + qid];
                    b[nj][1] = Bb[n * AST + k0 + qid + 4];
                }
                #pragma unroll
                for (int mi = 0; mi < 4; mi++)
                    #pragma unroll
                    for (int nj = 0; nj < 4; nj++)
                        mma_bf16(c[mi][nj], a[mi], b[nj]);
            }
            __syncthreads();
        }
        // epilogue: exp + row partial sums
        #pragma unroll
        for (int mi = 0; mi < 4; mi++) {
            float s0 = 0.f, s1 = 0.f;
            #pragma unroll
            for (int nj = 0; nj < 4; nj++) {
                int col = nc + wn + nj * 8 + 2 * qid;
                if (col < NHEAD)     { s0 += __expf(c[mi][nj][0]); s1 += __expf(c[mi][nj][2]); }
                if (col + 1 < NHEAD) { s0 += __expf(c[mi][nj][1]); s1 += __expf(c[mi][nj][3]); }
            }
            s0 += __shfl_xor_sync(0xffffffffu, s0, 1);
            s0 += __shfl_xor_sync(0xffffffffu, s0, 2);
            s1 += __shfl_xor_sync(0xffffffffu, s1, 1);
            s1 += __shfl_xor_sync(0xffffffffu, s1, 2);
            if (qid == 0) {
                atomicAdd(&rowAcc[wm + mi * 16 + grp], s0);
                atomicAdd(&rowAcc[wm + mi * 16 + grp + 8], s1);
            }
        }
    }
    __syncthreads();
    atomicAdd(&g_sum_head[row0 + tid], rowAcc[tid]);
}

// ---- TAILS: K<=256, A resident in smem; B whole-K tiles double-buffered -----
template<int K, int WHICH>
__global__ void __launch_bounds__(256, 1) expsum_tail() {
    extern __shared__ uint32_t sm[];
    const int ST = K / 2 + 4;             // u32 stride; ST%32==4; byte stride 16B-mult
    float* rowAcc = (float*)(sm + 256 * ST + 2 * 64 * ST);
    int* rowsId = (int*)(rowAcc + 256);

    int M; const int* idx; const __nv_bfloat16 *A, *B; int ncols;
    if (WHICH == 1) { M = g_cnt0; idx = g_idx0; A = g_proj0h; B = g_emb0h; ncols = SZ0; }
    else            { M = g_cnt1; idx = g_idx1; A = g_proj1h; B = g_emb1h; ncols = SZ1; }

    int row0 = blockIdx.x * 256;
    if (row0 >= M) return;
    int tid = threadIdx.x;
    int rid = row0 + tid; if (rid > M - 1) rid = M - 1;
    int myRow = idx[rid];
    rowsId[tid] = myRow;
    rowAcc[tid] = 0.f;

    uint32_t smBase = (uint32_t)__cvta_generic_to_shared(sm);
    uint32_t bBase[2] = { smBase + 256u * ST * 4, smBase + (256u * ST + 64u * ST) * 4 };

    {   // resident A preload (own row -> no sync needed before issuing)
        const char* aG = (const char*)(A + (size_t)myRow * K);
        uint32_t as = smBase + tid * ST * 4;
        #pragma unroll
        for (int s = 0; s < K / 8; s++) cp16(as + s * 16, aG + s * 16, true);
    }
    int bRowLoc = tid >> 2, bSegBase = (tid & 3) * 16;

    int warp = tid >> 5, lane = tid & 31, grp = lane >> 2, qid = lane & 3;
    int wm = (warp >> 1) * 64, wn = (warp & 1) * 32;

    int ncStride = gridDim.y * 64;
    int nc0 = blockIdx.y * 64;

    // B tile loader (whole K)
    auto loadB = [&](int nc, int buf) {
        int br = nc + bRowLoc;
        bool v = br < ncols;
        const char* bg = (const char*)(B + (size_t)(v ? br : 0) * K);
        uint32_t bs = bBase[buf] + bRowLoc * ST * 4 + bSegBase;
        #pragma unroll
        for (int j = 0; j < K / 32; j++) cp16(bs + j * 64, bg + bSegBase + j * 64, v);
    };
    loadB(nc0, 0); cpcommit();            // same group as A preload

    int buf = 0;
    for (int nc = nc0; nc < ncols; nc += ncStride) {
        if (nc + ncStride < ncols) { loadB(nc + ncStride, buf ^ 1); cpcommit(); cpwait<1>(); }
        else cpwait<0>();
        __syncthreads();

        float c[4][4][4];
        #pragma unroll
        for (int mi = 0; mi < 4; mi++)
            #pragma unroll
            for (int nj = 0; nj < 4; nj++)
                #pragma unroll
                for (int r = 0; r < 4; r++) c[mi][nj][r] = 0.f;

        const uint32_t* Ab = sm;
        const uint32_t* Bb = sm + 256 * ST + buf * 64 * ST;
        #pragma unroll
        for (int ks = 0; ks < K / 16; ks++) {
            int k0 = ks * 8;
            uint32_t a[4][4], b[4][2];
            #pragma unroll
            for (int mi = 0; mi < 4; mi++) {
                int r = wm + mi * 16 + grp;
                a[mi][0] = Ab[r * ST + k0 + qid];
                a[mi][1] = Ab[(r + 8) * ST + k0 + qid];
                a[mi][2] = Ab[r * ST + k0 + qid + 4];
                a[mi][3] = Ab[(r + 8) * ST + k0 + qid + 4];
            }
            #pragma unroll
            for (int nj = 0; nj < 4; nj++) {
                int n = wn + nj * 8 + grp;
                b[nj][0] = Bb[n * ST + k0 + qid];
                b[nj][1] = Bb[n * ST + k0 + qid + 4];
            }
            #pragma unroll
            for (int mi = 0; mi < 4; mi++)
                #pragma unroll
                for (int nj = 0; nj < 4; nj++)
                    mma_bf16(c[mi][nj], a[mi], b[nj]);
        }
        // epilogue
        #pragma unroll
        for (int mi = 0; mi < 4; mi++) {
            float s0 = 0.f, s1 = 0.f;
            #pragma unroll
            for (int nj = 0; nj < 4; nj++) {
                int col = nc + wn + nj * 8 + 2 * qid;
                if (col < ncols)     { s0 += __expf(c[mi][nj][0]); s1 += __expf(c[mi][nj][2]); }
                if (col + 1 < ncols) { s0 += __expf(c[mi][nj][1]); s1 += __expf(c[mi][nj][3]); }
            }
            s0 += __shfl_xor_sync(0xffffffffu, s0, 1);
            s0 += __shfl_xor_sync(0xffffffffu, s0, 2);
            s1 += __shfl_xor_sync(0xffffffffu, s1, 1);
            s1 += __shfl_xor_sync(0xffffffffu, s1, 2);
            if (qid == 0) {
                atomicAdd(&rowAcc[wm + mi * 16 + grp], s0);
                atomicAdd(&rowAcc[wm + mi * 16 + grp + 8], s1);
            }
        }
        __syncthreads();
        buf ^= 1;
    }
    if (row0 + tid < M) atomicAdd(&g_sum_tail[rowsId[tid]], rowAcc[tid]);
}

// ---------------- final gather ----------------------------------------------
__global__ void __launch_bounds__(256) final_kernel(
    const float* __restrict__ inputs, const int* __restrict__ targets,
    const float* __restrict__ head_W, const float* __restrict__ emb0,
    const float* __restrict__ emb1, float* __restrict__ out)
{
    int warp = (blockIdx.x * blockDim.x + threadIdx.x) >> 5;
    int lane = threadIdx.x & 31;
    if (warp >= NROWS) return;
    int row = warp;
    int t = targets[row];
    int ht = (t < CUT0) ? t : ((t < CUT1) ? CUT0 : CUT0 + 1);

    float s = 0.f;
    const float* x = inputs + (long)row * KDIM;
    const float* w = head_W + (long)ht * KDIM;
    for (int k = lane; k < KDIM; k += 32) s += x[k] * w[k];
    #pragma unroll
    for (int o = 16; o; o >>= 1) s += __shfl_xor_sync(0xffffffffu, s, o);
    float res = s - logf(g_sum_head[row]);

    if (t >= CUT0) {
        float tl = 0.f;
        if (t < CUT1) {
            const float* p = g_proj0 + (long)row * D0;
            const float* e = emb0 + (long)(t - CUT0) * D0;
            for (int k = lane; k < D0; k += 32) tl += p[k] * e[k];
        } else {
            const float* p = g_proj1 + (long)row * D1;
            const float* e = emb1 + (long)(t - CUT1) * D1;
            for (int k = lane; k < D1; k += 32) tl += p[k] * e[k];
        }
        #pragma unroll
        for (int o = 16; o; o >>= 1) tl += __shfl_xor_sync(0xffffffffu, tl, o);
        res += tl - logf(g_sum_tail[row]);
    }
    if (lane == 0) out[row] = res;
}

// -------- deterministic double-precision loss reduction ---------------------
__global__ void __launch_bounds__(1024) loss_kernel(float* __restrict__ out, int out_size) {
    __shared__ double sh[1024];
    int tid = threadIdx.x;
    double s = 0.0;
    for (int i = tid; i < NROWS; i += 1024) s += (double)out[i];
    sh[tid] = s;
    __syncthreads();
    for (int o = 512; o; o >>= 1) {
        if (tid < o) sh[tid] += sh[tid + o];
        __syncthreads();
    }
    if (tid == 0 && out_size > NROWS)
        out[out_size - 1] = (float)(-sh[0] / (double)NROWS);
}

// ---------------- launch -----------------------------------------------------
extern "C" void kernel_launch(void* const* d_in, const int* in_sizes, int n_in,
                              void* d_out, int out_size) {
    const float* inputs = 0; const int* targets = 0; const float* head_W = 0;
    const float* emb0 = 0; const float* lin0 = 0; const float* emb1 = 0; const float* lin1 = 0;
    for (int i = 0; i < n_in; i++) {
        switch (in_sizes[i]) {
            case NROWS * KDIM:  inputs  = (const float*)d_in[i]; break;
            case NROWS:         targets = (const int*)  d_in[i]; break;
            case NHEAD * KDIM:  head_W  = (const float*)d_in[i]; break;
            case SZ0 * D0:      emb0    = (const float*)d_in[i]; break;
            case KDIM * D0:     lin0    = (const float*)d_in[i]; break;
            case SZ1 * D1:      emb1    = (const float*)d_in[i]; break;
            case KDIM * D1:     lin1    = (const float*)d_in[i]; break;
        }
    }
    float* out = (float*)d_out;

    const int SMEM_HEAD = (2 * 5120 + 2 * 1280 + 256) * 4;
    const int SMEM_T0   = (256 * 132 + 2 * 64 * 132 + 512) * 4;  // K=256
    const int SMEM_T1   = (256 * 36 + 2 * 64 * 36 + 512) * 4;    // K=64
    cudaFuncSetAttribute(expsum_head, cudaFuncAttributeMaxDynamicSharedMemorySize, SMEM_HEAD);
    cudaFuncSetAttribute(expsum_tail<256, 1>, cudaFuncAttributeMaxDynamicSharedMemorySize, SMEM_T0);
    cudaFuncSetAttribute(expsum_tail<64, 2>,  cudaFuncAttributeMaxDynamicSharedMemorySize, SMEM_T1);

    init_kernel<<<16, 256>>>();
    classify_kernel<<<16, 256>>>(targets);

    cvt_kernel<<<1024, 256>>>(inputs, NROWS * KDIM, 0);
    cvt_kernel<<<1024, 256>>>(head_W, NHEAD * KDIM, 1);
    cvt_kernel<<<1024, 256>>>(emb0,   SZ0 * D0,     2);
    cvt_kernel<<<1024, 256>>>(emb1,   SZ1 * D1,     3);

    proj_kernel<<<dim3(NROWS / 64, D0 / 64), 256>>>(inputs, lin0, KDIM, D0, 0);
    proj_kernel<<<dim3(NROWS / 64, D1 / 64), 256>>>(inputs, lin1, KDIM, D1, 1);

    expsum_head<<<dim3(16, 32), 256, SMEM_HEAD>>>();
    expsum_tail<256, 1><<<dim3(16, 32), 256, SMEM_T0>>>();
    expsum_tail<64, 2><<<dim3(16, 32), 256, SMEM_T1>>>();

    final_kernel<<<(NROWS * 32) / 256, 256>>>(inputs, targets, head_W, emb0, emb1, out);
    loss_kernel<<<1, 1024>>>(out, out_size);
}

// round 7
// speedup vs baseline: 1.6116x; 1.6116x over previous
#include <cuda_runtime.h>
#include <cuda_bf16.h>
#include <math.h>
#include <stdint.h>

#define NROWS 4096
#define KDIM  1024
#define NHEAD 2002
#define CUT0  2000
#define CUT1  10000
#define NTOK  50257
#define SZ0   8000
#define SZ1   40257
#define D0    256
#define D1    64

// ---------------- scratch (device globals; no allocation allowed) -----------
__device__ float g_proj0[NROWS * D0];
__device__ float g_proj1[NROWS * D1];
__device__ float g_sum_head[NROWS];
__device__ float g_sum_tail[NROWS];
__device__ int   g_idx0[NROWS];
__device__ int   g_idx1[NROWS];
__device__ int   g_cnt0, g_cnt1;

__device__ __align__(16) __nv_bfloat16 g_inh[NROWS * KDIM];
__device__ __align__(16) __nv_bfloat16 g_headWh[NHEAD * KDIM];
__device__ __align__(16) __nv_bfloat16 g_emb0h[SZ0 * D0];
__device__ __align__(16) __nv_bfloat16 g_emb1h[SZ1 * D1];
__device__ __align__(16) __nv_bfloat16 g_proj0h[NROWS * D0];
__device__ __align__(16) __nv_bfloat16 g_proj1h[NROWS * D1];

// ---------------- helpers ----------------------------------------------------
__device__ __forceinline__ void cp16(uint32_t s, const void* g, bool v) {
    if (v) asm volatile("cp.async.cg.shared.global [%0], [%1], 16;\n" :: "r"(s), "l"(g));
    else   asm volatile("cp.async.cg.shared.global [%0], [%1], 16, 0;\n" :: "r"(s), "l"(g));
}
__device__ __forceinline__ void cpcommit() { asm volatile("cp.async.commit_group;\n"); }
template<int N> __device__ __forceinline__ void cpwait() {
    asm volatile("cp.async.wait_group %0;\n" :: "n"(N));
}
__device__ __forceinline__ void mma_bf16(float c[4], const uint32_t a[4], const uint32_t b[2]) {
    asm volatile(
        "mma.sync.aligned.m16n8k16.row.col.f32.bf16.bf16.f32 "
        "{%0,%1,%2,%3}, {%4,%5,%6,%7}, {%8,%9}, {%0,%1,%2,%3};"
        : "+f"(c[0]), "+f"(c[1]), "+f"(c[2]), "+f"(c[3])
        : "r"(a[0]), "r"(a[1]), "r"(a[2]), "r"(a[3]), "r"(b[0]), "r"(b[1]));
}
__device__ __forceinline__ void ldsm4(uint32_t r[4], uint32_t addr) {
    asm volatile("ldmatrix.sync.aligned.m8n8.x4.shared.b16 {%0,%1,%2,%3}, [%4];"
        : "=r"(r[0]), "=r"(r[1]), "=r"(r[2]), "=r"(r[3]) : "r"(addr));
}

// ---------------- init / classify / convert ---------------------------------
__global__ void init_kernel() {
    int i = blockIdx.x * blockDim.x + threadIdx.x;
    if (i < NROWS) { g_sum_head[i] = 0.f; g_sum_tail[i] = 0.f; }
    if (i == 0) { g_cnt0 = 0; g_cnt1 = 0; }
}

__global__ void classify_kernel(const int* __restrict__ targets) {
    int i = blockIdx.x * blockDim.x + threadIdx.x;
    if (i >= NROWS) return;
    int t = targets[i];
    if (t >= CUT0 && t < CUT1) { int p = atomicAdd(&g_cnt0, 1); g_idx0[p] = i; }
    else if (t >= CUT1)        { int p = atomicAdd(&g_cnt1, 1); g_idx1[p] = i; }
}

__global__ void cvt_all(const float* __restrict__ i0, const float* __restrict__ i1,
                        const float* __restrict__ i2, const float* __restrict__ i3) {
    int t = blockIdx.x * blockDim.x + threadIdx.x;
    int gs = gridDim.x * blockDim.x;
    const float* srcs[4] = { i0, i1, i2, i3 };
    __nv_bfloat16* dsts[4] = { g_inh, g_headWh, g_emb0h, g_emb1h };
    const int n4s[4] = { NROWS * KDIM / 4, NHEAD * KDIM / 4, SZ0 * D0 / 4, SZ1 * D1 / 4 };
    #pragma unroll
    for (int a = 0; a < 4; a++) {
        const float4* s = (const float4*)srcs[a];
        __nv_bfloat162* d = (__nv_bfloat162*)dsts[a];
        for (int i = t; i < n4s[a]; i += gs) {
            float4 v = s[i];
            d[2 * i]     = __floats2bfloat162_rn(v.x, v.y);
            d[2 * i + 1] = __floats2bfloat162_rn(v.z, v.w);
        }
    }
}

// ---------------- projection GEMM (fp32 out + bf16 copy) --------------------
__global__ void __launch_bounds__(256) proj_kernel(
    const float* __restrict__ A, const float* __restrict__ B,
    int K, int dout, int which)
{
    __shared__ float As[64][68];
    __shared__ float Bs[64][68];
    float* __restrict__ P = (which == 0) ? g_proj0 : g_proj1;
    __nv_bfloat16* __restrict__ Ph = (which == 0) ? g_proj0h : g_proj1h;

    int tid = threadIdx.x;
    int tx = tid & 15, ty = tid >> 4;
    int row0 = blockIdx.x * 64;
    int nc   = blockIdx.y * 64;

    float acc[4][4] = {};
    for (int kc = 0; kc < K; kc += 64) {
        __syncthreads();
        {
            int r = tid >> 2, q = tid & 3;
            const float* ga = A + (long)(row0 + r) * K + kc;
            #pragma unroll
            for (int j = 0; j < 4; j++) {
                int c = (q + 4 * j) * 4;
                *reinterpret_cast<float4*>(&As[r][c]) =
                    *reinterpret_cast<const float4*>(ga + c);
            }
        }
        {
            int k = tid >> 2, q = tid & 3;
            const float* gb = B + (long)(kc + k) * dout + nc;
            #pragma unroll
            for (int j = 0; j < 4; j++) {
                int c = (q + 4 * j) * 4;
                *reinterpret_cast<float4*>(&Bs[k][c]) =
                    *reinterpret_cast<const float4*>(gb + c);
            }
        }
        __syncthreads();
        #pragma unroll
        for (int k = 0; k < 64; k++) {
            float4 b = *reinterpret_cast<float4*>(&Bs[k][tx * 4]);
            float a0 = As[ty * 4 + 0][k], a1 = As[ty * 4 + 1][k];
            float a2 = As[ty * 4 + 2][k], a3 = As[ty * 4 + 3][k];
            acc[0][0] += a0 * b.x; acc[0][1] += a0 * b.y; acc[0][2] += a0 * b.z; acc[0][3] += a0 * b.w;
            acc[1][0] += a1 * b.x; acc[1][1] += a1 * b.y; acc[1][2] += a1 * b.z; acc[1][3] += a1 * b.w;
            acc[2][0] += a2 * b.x; acc[2][1] += a2 * b.y; acc[2][2] += a2 * b.z; acc[2][3] += a2 * b.w;
            acc[3][0] += a3 * b.x; acc[3][1] += a3 * b.y; acc[3][2] += a3 * b.z; acc[3][3] += a3 * b.w;
        }
    }
    #pragma unroll
    for (int i = 0; i < 4; i++) {
        long off = (long)(row0 + ty * 4 + i) * dout + nc + tx * 4;
        float4 v = make_float4(acc[i][0], acc[i][1], acc[i][2], acc[i][3]);
        *reinterpret_cast<float4*>(&P[off]) = v;
        *reinterpret_cast<__nv_bfloat162*>(&Ph[off])     = __floats2bfloat162_rn(v.x, v.y);
        *reinterpret_cast<__nv_bfloat162*>(&Ph[off + 2]) = __floats2bfloat162_rn(v.z, v.w);
    }
}

// ======================= bf16 tensor-core exp-sum (ldmatrix) =================
// Block 256 x 128 (head, tail1) / 256 x 64 (tail0); 8 warps 4m x 2n.

// ---- HEAD: K=1024, k-chunk 32, A+B cp.async double-buffered -----------------
__global__ void __launch_bounds__(256) expsum_head() {
    extern __shared__ uint32_t sm[];
    const int AST = 20;  // 16 data u32 + 4 pad (80B rows: LDSM conflict-free)
    // A[2][256*20] | B[2][128*20] | rowAcc[256]
    float* rowAcc = (float*)(sm + 15360);
    uint32_t smB = (uint32_t)__cvta_generic_to_shared(sm);
    const uint32_t aOff[2] = { 0u, 5120u * 4 };
    const uint32_t bOff[2] = { 10240u * 4, 12800u * 4 };

    int tid = threadIdx.x;
    rowAcc[tid] = 0.f;
    int row0 = blockIdx.x * 256;
    int warp = tid >> 5, lane = tid & 31, grp = lane >> 2, qid = lane & 3;
    int wm = (warp >> 1) * 64, wn = (warp & 1) * 64;
    int nc = blockIdx.y * 128;

    const char* aG = (const char*)(g_inh + (size_t)(row0 + tid) * KDIM);
    int bRow = tid >> 1, bSeg = (tid & 1) * 32;
    int bGRow = nc + bRow;
    bool bv = bGRow < NHEAD;
    const char* bG = (const char*)(g_headWh + (size_t)(bv ? bGRow : 0) * KDIM);

    uint32_t aLd = (uint32_t)((wm + (lane & 15)) * AST + (lane >> 4) * 4) * 4;
    uint32_t bLd = (uint32_t)((wn + ((lane >> 4) & 1) * 8 + (lane & 7)) * AST
                              + ((lane >> 3) & 1) * 4) * 4;

    float c[4][8][4] = {};

    {   // chunk 0
        uint32_t as = smB + aOff[0] + (uint32_t)tid * AST * 4;
        #pragma unroll
        for (int s = 0; s < 4; s++) cp16(as + s * 16, aG + s * 16, true);
        uint32_t bs = smB + bOff[0] + (uint32_t)bRow * AST * 4 + bSeg;
        cp16(bs,      bG + bSeg,      bv);
        cp16(bs + 16, bG + bSeg + 16, bv);
        cpcommit();
    }
    const int NCH = KDIM / 32;
    for (int ch = 0; ch < NCH; ch++) {
        int cur = ch & 1;
        if (ch + 1 < NCH) {
            int nb = cur ^ 1;
            uint32_t as = smB + aOff[nb] + (uint32_t)tid * AST * 4;
            const char* ag = aG + (ch + 1) * 64;
            #pragma unroll
            for (int s = 0; s < 4; s++) cp16(as + s * 16, ag + s * 16, true);
            uint32_t bs = smB + bOff[nb] + (uint32_t)bRow * AST * 4 + bSeg;
            cp16(bs,      bG + (ch + 1) * 64 + bSeg,      bv);
            cp16(bs + 16, bG + (ch + 1) * 64 + bSeg + 16, bv);
            cpcommit(); cpwait<1>();
        } else cpwait<0>();
        __syncthreads();
        uint32_t aT = smB + aOff[cur] + aLd;
        uint32_t bT = smB + bOff[cur] + bLd;
        #pragma unroll
        for (int ks = 0; ks < 2; ks++) {
            uint32_t a[4][4], b[8][2];
            #pragma unroll
            for (int mi = 0; mi < 4; mi++)
                ldsm4(a[mi], aT + (uint32_t)(mi * 16 * AST + ks * 8) * 4);
            #pragma unroll
            for (int p = 0; p < 4; p++) {
                uint32_t r[4];
                ldsm4(r, bT + (uint32_t)(p * 16 * AST + ks * 8) * 4);
                b[2 * p][0] = r[0]; b[2 * p][1] = r[1];
                b[2 * p + 1][0] = r[2]; b[2 * p + 1][1] = r[3];
            }
            #pragma unroll
            for (int mi = 0; mi < 4; mi++)
                #pragma unroll
                for (int nj = 0; nj < 8; nj++)
                    mma_bf16(c[mi][nj], a[mi], b[nj]);
        }
        __syncthreads();
    }
    // epilogue
    #pragma unroll
    for (int mi = 0; mi < 4; mi++) {
        float s0 = 0.f, s1 = 0.f;
        #pragma unroll
        for (int nj = 0; nj < 8; nj++) {
            int col = nc + wn + nj * 8 + 2 * qid;
            if (col < NHEAD)     { s0 += __expf(c[mi][nj][0]); s1 += __expf(c[mi][nj][2]); }
            if (col + 1 < NHEAD) { s0 += __expf(c[mi][nj][1]); s1 += __expf(c[mi][nj][3]); }
        }
        s0 += __shfl_xor_sync(0xffffffffu, s0, 1);
        s0 += __shfl_xor_sync(0xffffffffu, s0, 2);
        s1 += __shfl_xor_sync(0xffffffffu, s1, 1);
        s1 += __shfl_xor_sync(0xffffffffu, s1, 2);
        if (qid == 0) {
            atomicAdd(&rowAcc[wm + mi * 16 + grp], s0);
            atomicAdd(&rowAcc[wm + mi * 16 + grp + 8], s1);
        }
    }
    __syncthreads();
    atomicAdd(&g_sum_head[row0 + tid], rowAcc[tid]);
}

// ---- TAILS: A resident in smem, B whole-K tiles double-buffered -------------
template<int K, int NBLK, int WHICH>
__global__ void __launch_bounds__(256) expsum_tail() {
    extern __shared__ uint32_t sm[];
    const int ST = K / 2 + 4;
    const int NJ = NBLK / 16;
    const int WN = NBLK / 2;
    float* rowAcc = (float*)(sm + 256 * ST + 2 * NBLK * ST);
    int* rowsId = (int*)(rowAcc + 256);

    int M; const int* idx; const __nv_bfloat16 *A, *B; int ncols;
    if (WHICH == 1) { M = g_cnt0; idx = g_idx0; A = g_proj0h; B = g_emb0h; ncols = SZ0; }
    else            { M = g_cnt1; idx = g_idx1; A = g_proj1h; B = g_emb1h; ncols = SZ1; }

    int row0 = blockIdx.x * 256;
    if (row0 >= M) return;
    int tid = threadIdx.x;
    int rid = row0 + tid; if (rid > M - 1) rid = M - 1;
    int myRow = idx[rid];
    rowsId[tid] = myRow;
    rowAcc[tid] = 0.f;

    uint32_t smB = (uint32_t)__cvta_generic_to_shared(sm);
    const uint32_t bOff[2] = { 256u * ST * 4, (256u + NBLK) * ST * 4 };

    {   // resident A preload (own row)
        const char* aG = (const char*)(A + (size_t)myRow * K);
        uint32_t as = smB + (uint32_t)tid * ST * 4;
        #pragma unroll
        for (int s = 0; s < K / 8; s++) cp16(as + s * 16, aG + s * 16, true);
    }
    const int TPR = 256 / NBLK;                // threads per B row
    const int SEGB = 2 * K / TPR;              // bytes per thread
    int bRow = tid / TPR, bSeg = (tid % TPR) * SEGB;

    int warp = tid >> 5, lane = tid & 31, grp = lane >> 2, qid = lane & 3;
    int wm = (warp >> 1) * 64, wn = (warp & 1) * WN;

    uint32_t aLd = (uint32_t)((wm + (lane & 15)) * ST + (lane >> 4) * 4) * 4;
    uint32_t bLd = (uint32_t)((wn + ((lane >> 4) & 1) * 8 + (lane & 7)) * ST
                              + ((lane >> 3) & 1) * 4) * 4;

    int ncStride = gridDim.y * NBLK;
    int nc0 = blockIdx.y * NBLK;

    auto loadB = [&](int nc, int buf) {
        int br = nc + bRow;
        bool v = br < ncols;
        const char* bg = (const char*)(B + (size_t)(v ? br : 0) * K) + bSeg;
        uint32_t bs = smB + bOff[buf] + (uint32_t)bRow * ST * 4 + bSeg;
        #pragma unroll
        for (int j = 0; j < SEGB / 16; j++) cp16(bs + j * 16, bg + j * 16, v);
    };
    if (nc0 < ncols) loadB(nc0, 0);
    cpcommit();

    int buf = 0;
    for (int nc = nc0; nc < ncols; nc += ncStride) {
        if (nc + ncStride < ncols) { loadB(nc + ncStride, buf ^ 1); cpcommit(); cpwait<1>(); }
        else cpwait<0>();
        __syncthreads();

        float c[4][NJ][4];
        #pragma unroll
        for (int mi = 0; mi < 4; mi++)
            #pragma unroll
            for (int nj = 0; nj < NJ; nj++)
                #pragma unroll
                for (int r = 0; r < 4; r++) c[mi][nj][r] = 0.f;

        uint32_t aT = smB + aLd;
        uint32_t bT = smB + bOff[buf] + bLd;
        #pragma unroll
        for (int ks = 0; ks < K / 16; ks++) {
            uint32_t a[4][4], b[NJ][2];
            #pragma unroll
            for (int mi = 0; mi < 4; mi++)
                ldsm4(a[mi], aT + (uint32_t)(mi * 16 * ST + ks * 8) * 4);
            #pragma unroll
            for (int p = 0; p < NJ / 2; p++) {
                uint32_t r[4];
                ldsm4(r, bT + (uint32_t)(p * 16 * ST + ks * 8) * 4);
                b[2 * p][0] = r[0]; b[2 * p][1] = r[1];
                b[2 * p + 1][0] = r[2]; b[2 * p + 1][1] = r[3];
            }
            #pragma unroll
            for (int mi = 0; mi < 4; mi++)
                #pragma unroll
                for (int nj = 0; nj < NJ; nj++)
                    mma_bf16(c[mi][nj], a[mi], b[nj]);
        }
        // epilogue
        #pragma unroll
        for (int mi = 0; mi < 4; mi++) {
            float s0 = 0.f, s1 = 0.f;
            #pragma unroll
            for (int nj = 0; nj < NJ; nj++) {
                int col = nc + wn + nj * 8 + 2 * qid;
                if (col < ncols)     { s0 += __expf(c[mi][nj][0]); s1 += __expf(c[mi][nj][2]); }
                if (col + 1 < ncols) { s0 += __expf(c[mi][nj][1]); s1 += __expf(c[mi][nj][3]); }
            }
            s0 += __shfl_xor_sync(0xffffffffu, s0, 1);
            s0 += __shfl_xor_sync(0xffffffffu, s0, 2);
            s1 += __shfl_xor_sync(0xffffffffu, s1, 1);
            s1 += __shfl_xor_sync(0xffffffffu, s1, 2);
            if (qid == 0) {
                atomicAdd(&rowAcc[wm + mi * 16 + grp], s0);
                atomicAdd(&rowAcc[wm + mi * 16 + grp + 8], s1);
            }
        }
        __syncthreads();
        buf ^= 1;
    }
    if (row0 + tid < M) atomicAdd(&g_sum_tail[rowsId[tid]], rowAcc[tid]);
}

// ---------------- final gather ----------------------------------------------
__global__ void __launch_bounds__(256) final_kernel(
    const float* __restrict__ inputs, const int* __restrict__ targets,
    const float* __restrict__ head_W, const float* __restrict__ emb0,
    const float* __restrict__ emb1, float* __restrict__ out)
{
    int warp = (blockIdx.x * blockDim.x + threadIdx.x) >> 5;
    int lane = threadIdx.x & 31;
    if (warp >= NROWS) return;
    int row = warp;
    int t = targets[row];
    int ht = (t < CUT0) ? t : ((t < CUT1) ? CUT0 : CUT0 + 1);

    float s = 0.f;
    const float* x = inputs + (long)row * KDIM;
    const float* w = head_W + (long)ht * KDIM;
    for (int k = lane; k < KDIM; k += 32) s += x[k] * w[k];
    #pragma unroll
    for (int o = 16; o; o >>= 1) s += __shfl_xor_sync(0xffffffffu, s, o);
    float res = s - logf(g_sum_head[row]);

    if (t >= CUT0) {
        float tl = 0.f;
        if (t < CUT1) {
            const float* p = g_proj0 + (long)row * D0;
            const float* e = emb0 + (long)(t - CUT0) * D0;
            for (int k = lane; k < D0; k += 32) tl += p[k] * e[k];
        } else {
            const float* p = g_proj1 + (long)row * D1;
            const float* e = emb1 + (long)(t - CUT1) * D1;
            for (int k = lane; k < D1; k += 32) tl += p[k] * e[k];
        }
        #pragma unroll
        for (int o = 16; o; o >>= 1) tl += __shfl_xor_sync(0xffffffffu, tl, o);
        res += tl - logf(g_sum_tail[row]);
    }
    if (lane == 0) out[row] = res;
}

// -------- deterministic double-precision loss reduction ---------------------
__global__ void __launch_bounds__(1024) loss_kernel(float* __restrict__ out, int out_size) {
    __shared__ double sh[1024];
    int tid = threadIdx.x;
    double s = 0.0;
    for (int i = tid; i < NROWS; i += 1024) s += (double)out[i];
    sh[tid] = s;
    __syncthreads();
    for (int o = 512; o; o >>= 1) {
        if (tid < o) sh[tid] += sh[tid + o];
        __syncthreads();
    }
    if (tid == 0 && out_size > NROWS)
        out[out_size - 1] = (float)(-sh[0] / (double)NROWS);
}

// ---------------- launch -----------------------------------------------------
extern "C" void kernel_launch(void* const* d_in, const int* in_sizes, int n_in,
                              void* d_out, int out_size) {
    const float* inputs = 0; const int* targets = 0; const float* head_W = 0;
    const float* emb0 = 0; const float* lin0 = 0; const float* emb1 = 0; const float* lin1 = 0;
    for (int i = 0; i < n_in; i++) {
        switch (in_sizes[i]) {
            case NROWS * KDIM:  inputs  = (const float*)d_in[i]; break;
            case NROWS:         targets = (const int*)  d_in[i]; break;
            case NHEAD * KDIM:  head_W  = (const float*)d_in[i]; break;
            case SZ0 * D0:      emb0    = (const float*)d_in[i]; break;
            case KDIM * D0:     lin0    = (const float*)d_in[i]; break;
            case SZ1 * D1:      emb1    = (const float*)d_in[i]; break;
            case KDIM * D1:     lin1    = (const float*)d_in[i]; break;
        }
    }
    float* out = (float*)d_out;

    const int SMEM_HEAD = (2 * 5120 + 2 * 2560 + 256) * 4;                       // 62.5 KB
    const int SMEM_T0   = (256 * 132 + 2 * 64 * 132 + 512) * 4;                  // 203 KB
    const int SMEM_T1   = (256 * 36 + 2 * 128 * 36 + 512) * 4;                   // 75 KB
    cudaFuncSetAttribute(expsum_head, cudaFuncAttributeMaxDynamicSharedMemorySize, SMEM_HEAD);
    cudaFuncSetAttribute(expsum_tail<256, 64, 1>, cudaFuncAttributeMaxDynamicSharedMemorySize, SMEM_T0);
    cudaFuncSetAttribute(expsum_tail<64, 128, 2>, cudaFuncAttributeMaxDynamicSharedMemorySize, SMEM_T1);

    init_kernel<<<16, 256>>>();
    classify_kernel<<<16, 256>>>(targets);
    cvt_all<<<2048, 256>>>(inputs, head_W, emb0, emb1);

    proj_kernel<<<dim3(NROWS / 64, D0 / 64), 256>>>(inputs, lin0, KDIM, D0, 0);
    proj_kernel<<<dim3(NROWS / 64, D1 / 64), 256>>>(inputs, lin1, KDIM, D1, 1);

    expsum_head<<<dim3(16, 16), 256, SMEM_HEAD>>>();
    expsum_tail<256, 64, 1><<<dim3(16, 63), 256, SMEM_T0>>>();
    expsum_tail<64, 128, 2><<<dim3(16, 20), 256, SMEM_T1>>>();

    final_kernel<<<(NROWS * 32) / 256, 256>>>(inputs, targets, head_W, emb0, emb1, out);
    loss_kernel<<<1, 1024>>>(out, out_size);
}

// round 10
// speedup vs baseline: 1.7194x; 1.0669x over previous
#include <cuda_runtime.h>
#include <cuda_bf16.h>
#include <math.h>
#include <stdint.h>

#define NROWS 4096
#define KDIM  1024
#define NHEAD 2002
#define CUT0  2000
#define CUT1  10000
#define NTOK  50257
#define SZ0   8000
#define SZ1   40257
#define D0    256
#define D1    64

// ---------------- scratch (device globals; no allocation allowed) -----------
__device__ float g_proj0[NROWS * D0];
__device__ float g_proj1[NROWS * D1];
__device__ float g_sum_head[NROWS];
__device__ float g_sum_tail[NROWS];
__device__ int   g_idx0[NROWS];
__device__ int   g_idx1[NROWS];
__device__ int   g_cnt0, g_cnt1;

__device__ __align__(16) __nv_bfloat16 g_inh[NROWS * KDIM];
__device__ __align__(16) __nv_bfloat16 g_headWh[NHEAD * KDIM];
__device__ __align__(16) __nv_bfloat16 g_emb0h[SZ0 * D0];
__device__ __align__(16) __nv_bfloat16 g_emb1h[SZ1 * D1];
__device__ __align__(16) __nv_bfloat16 g_proj0h[NROWS * D0];
__device__ __align__(16) __nv_bfloat16 g_proj1h[NROWS * D1];
__device__ __align__(16) __nv_bfloat16 g_lin0t[D0 * KDIM];   // [n][k]
__device__ __align__(16) __nv_bfloat16 g_lin1t[D1 * KDIM];   // [n][k]

// ---------------- helpers ----------------------------------------------------
__device__ __forceinline__ void cp16(uint32_t s, const void* g, bool v) {
    if (v) asm volatile("cp.async.cg.shared.global [%0], [%1], 16;\n" :: "r"(s), "l"(g));
    else   asm volatile("cp.async.cg.shared.global [%0], [%1], 16, 0;\n" :: "r"(s), "l"(g));
}
__device__ __forceinline__ void cpcommit() { asm volatile("cp.async.commit_group;\n"); }
template<int N> __device__ __forceinline__ void cpwait() {
    asm volatile("cp.async.wait_group %0;\n" :: "n"(N));
}
__device__ __forceinline__ void mma_bf16(float c[4], const uint32_t a[4], const uint32_t b[2]) {
    asm volatile(
        "mma.sync.aligned.m16n8k16.row.col.f32.bf16.bf16.f32 "
        "{%0,%1,%2,%3}, {%4,%5,%6,%7}, {%8,%9}, {%0,%1,%2,%3};"
        : "+f"(c[0]), "+f"(c[1]), "+f"(c[2]), "+f"(c[3])
        : "r"(a[0]), "r"(a[1]), "r"(a[2]), "r"(a[3]), "r"(b[0]), "r"(b[1]));
}
__device__ __forceinline__ void ldsm4(uint32_t r[4], uint32_t addr) {
    asm volatile("ldmatrix.sync.aligned.m8n8.x4.shared.b16 {%0,%1,%2,%3}, [%4];"
        : "=r"(r[0]), "=r"(r[1]), "=r"(r[2]), "=r"(r[3]) : "r"(addr));
}

// ---------------- init / classify / convert ---------------------------------
__global__ void init_kernel() {
    int i = blockIdx.x * blockDim.x + threadIdx.x;
    if (i < NROWS) { g_sum_head[i] = 0.f; g_sum_tail[i] = 0.f; }
    if (i == 0) { g_cnt0 = 0; g_cnt1 = 0; }
}

__global__ void classify_kernel(const int* __restrict__ targets) {
    int i = blockIdx.x * blockDim.x + threadIdx.x;
    if (i >= NROWS) return;
    int t = targets[i];
    if (t >= CUT0 && t < CUT1) { int p = atomicAdd(&g_cnt0, 1); g_idx0[p] = i; }
    else if (t >= CUT1)        { int p = atomicAdd(&g_cnt1, 1); g_idx1[p] = i; }
}

__global__ void cvt_all(const float* __restrict__ i0, const float* __restrict__ i1,
                        const float* __restrict__ i2, const float* __restrict__ i3) {
    int t = blockIdx.x * blockDim.x + threadIdx.x;
    int gs = gridDim.x * blockDim.x;
    const float* srcs[4] = { i0, i1, i2, i3 };
    __nv_bfloat16* dsts[4] = { g_inh, g_headWh, g_emb0h, g_emb1h };
    const int n4s[4] = { NROWS * KDIM / 4, NHEAD * KDIM / 4, SZ0 * D0 / 4, SZ1 * D1 / 4 };
    #pragma unroll
    for (int a = 0; a < 4; a++) {
        const float4* s = (const float4*)srcs[a];
        __nv_bfloat162* d = (__nv_bfloat162*)dsts[a];
        for (int i = t; i < n4s[a]; i += gs) {
            float4 v = s[i];
            d[2 * i]     = __floats2bfloat162_rn(v.x, v.y);
            d[2 * i + 1] = __floats2bfloat162_rn(v.z, v.w);
        }
    }
}

// transpose lin[k][n] -> bf16 lint[n][k] (small, L2-resident source)
__global__ void cvt_lin(const float* __restrict__ lin0, const float* __restrict__ lin1) {
    int t = blockIdx.x * blockDim.x + threadIdx.x;
    int gs = gridDim.x * blockDim.x;
    for (int i = t; i < D0 * KDIM; i += gs) {
        int n = i >> 10, k = i & (KDIM - 1);
        g_lin0t[i] = __float2bfloat16(lin0[k * D0 + n]);
    }
    for (int i = t; i < D1 * KDIM; i += gs) {
        int n = i >> 10, k = i & (KDIM - 1);
        g_lin1t[i] = __float2bfloat16(lin1[k * D1 + n]);
    }
}

// ---------------- tensor-core projection GEMM -------------------------------
// P[4096][NOUT] = inputs(bf16) @ linT(bf16)^T ; writes fp32 P + bf16 Ph.
// Block 256 rows x NBLK cols, 8 warps 4m x 2n, k-chunk 32 double-buffered.
template<int NOUT, int NBLK, int WHICH>
__global__ void __launch_bounds__(256) proj_mma() {
    extern __shared__ uint32_t sm[];
    const int AST = 20;
    const int NJ = NBLK / 16;
    uint32_t smB = (uint32_t)__cvta_generic_to_shared(sm);
    const uint32_t aOff[2] = { 0u, 5120u * 4 };
    const uint32_t bOff[2] = { 10240u * 4, (10240u + NBLK * AST) * 4 };

    float* __restrict__ P = (WHICH == 0) ? g_proj0 : g_proj1;
    __nv_bfloat16* __restrict__ Ph = (WHICH == 0) ? g_proj0h : g_proj1h;
    const __nv_bfloat16* __restrict__ Bt = (WHICH == 0) ? g_lin0t : g_lin1t;

    int tid = threadIdx.x;
    int row0 = blockIdx.x * 256;
    int nc = blockIdx.y * NBLK;
    int warp = tid >> 5, lane = tid & 31, grp = lane >> 2, qid = lane & 3;
    int wm = (warp >> 1) * 64, wn = (warp & 1) * (NBLK / 2);

    const char* aG = (const char*)(g_inh + (size_t)(row0 + tid) * KDIM);
    const int TPR = 256 / NBLK;           // threads per B row
    const int SEG = 64 / TPR;             // bytes per thread per chunk
    int bRow = tid / TPR, bSeg = (tid % TPR) * SEG;
    const char* bG = (const char*)(Bt + (size_t)(nc + bRow) * KDIM);

    uint32_t aLd = (uint32_t)((wm + (lane & 15)) * AST + (lane >> 4) * 4) * 4;
    uint32_t bLd = (uint32_t)((wn + ((lane >> 4) & 1) * 8 + (lane & 7)) * AST
                              + ((lane >> 3) & 1) * 4) * 4;

    float c[4][NJ][4];
    #pragma unroll
    for (int mi = 0; mi < 4; mi++)
        #pragma unroll
        for (int nj = 0; nj < NJ; nj++)
            #pragma unroll
            for (int r = 0; r < 4; r++) c[mi][nj][r] = 0.f;

    {   // chunk 0
        uint32_t as = smB + aOff[0] + (uint32_t)tid * AST * 4;
        #pragma unroll
        for (int s = 0; s < 4; s++) cp16(as + s * 16, aG + s * 16, true);
        uint32_t bs = smB + bOff[0] + (uint32_t)bRow * AST * 4 + bSeg;
        #pragma unroll
        for (int s = 0; s < SEG / 16; s++) cp16(bs + s * 16, bG + bSeg + s * 16, true);
        cpcommit();
    }
    const int NCH = KDIM / 32;
    for (int ch = 0; ch < NCH; ch++) {
        int cur = ch & 1;
        if (ch + 1 < NCH) {
            int nb = cur ^ 1;
            uint32_t as = smB + aOff[nb] + (uint32_t)tid * AST * 4;
            const char* ag = aG + (ch + 1) * 64;
            #pragma unroll
            for (int s = 0; s < 4; s++) cp16(as + s * 16, ag + s * 16, true);
            uint32_t bs = smB + bOff[nb] + (uint32_t)bRow * AST * 4 + bSeg;
            const char* bg = bG + (ch + 1) * 64 + bSeg;
            #pragma unroll
            for (int s = 0; s < SEG / 16; s++) cp16(bs + s * 16, bg + s * 16, true);
            cpcommit(); cpwait<1>();
        } else cpwait<0>();
        __syncthreads();
        uint32_t aT = smB + aOff[cur] + aLd;
        uint32_t bT = smB + bOff[cur] + bLd;
        #pragma unroll
        for (int ks = 0; ks < 2; ks++) {
            uint32_t a[4][4], b[NJ][2];
            #pragma unroll
            for (int mi = 0; mi < 4; mi++)
                ldsm4(a[mi], aT + (uint32_t)(mi * 16 * AST + ks * 8) * 4);
            #pragma unroll
            for (int p = 0; p < NJ / 2; p++) {
                uint32_t r[4];
                ldsm4(r, bT + (uint32_t)(p * 16 * AST + ks * 8) * 4);
                b[2 * p][0] = r[0]; b[2 * p][1] = r[1];
                b[2 * p + 1][0] = r[2]; b[2 * p + 1][1] = r[3];
            }
            #pragma unroll
            for (int mi = 0; mi < 4; mi++)
                #pragma unroll
                for (int nj = 0; nj < NJ; nj++)
                    mma_bf16(c[mi][nj], a[mi], b[nj]);
        }
        __syncthreads();
    }
    // epilogue: store fp32 + bf16
    #pragma unroll
    for (int mi = 0; mi < 4; mi++) {
        #pragma unroll
        for (int nj = 0; nj < NJ; nj++) {
            int r0 = row0 + wm + mi * 16 + grp;
            int col = nc + wn + nj * 8 + 2 * qid;
            long o0 = (long)r0 * NOUT + col;
            long o1 = (long)(r0 + 8) * NOUT + col;
            *reinterpret_cast<float2*>(&P[o0]) = make_float2(c[mi][nj][0], c[mi][nj][1]);
            *reinterpret_cast<float2*>(&P[o1]) = make_float2(c[mi][nj][2], c[mi][nj][3]);
            *reinterpret_cast<__nv_bfloat162*>(&Ph[o0]) =
                __floats2bfloat162_rn(c[mi][nj][0], c[mi][nj][1]);
            *reinterpret_cast<__nv_bfloat162*>(&Ph[o1]) =
                __floats2bfloat162_rn(c[mi][nj][2], c[mi][nj][3]);
        }
    }
}

// ======================= bf16 tensor-core exp-sum (ldmatrix) =================

// ---- HEAD: K=1024, k-chunk 32, A+B cp.async double-buffered -----------------
__global__ void __launch_bounds__(256) expsum_head() {
    extern __shared__ uint32_t sm[];
    const int AST = 20;
    float* rowAcc = (float*)(sm + 15360);
    uint32_t smB = (uint32_t)__cvta_generic_to_shared(sm);
    const uint32_t aOff[2] = { 0u, 5120u * 4 };
    const uint32_t bOff[2] = { 10240u * 4, 12800u * 4 };

    int tid = threadIdx.x;
    rowAcc[tid] = 0.f;
    int row0 = blockIdx.x * 256;
    int warp = tid >> 5, lane = tid & 31, grp = lane >> 2, qid = lane & 3;
    int wm = (warp >> 1) * 64, wn = (warp & 1) * 64;
    int nc = blockIdx.y * 128;

    const char* aG = (const char*)(g_inh + (size_t)(row0 + tid) * KDIM);
    int bRow = tid >> 1, bSeg = (tid & 1) * 32;
    int bGRow = nc + bRow;
    bool bv = bGRow < NHEAD;
    const char* bG = (const char*)(g_headWh + (size_t)(bv ? bGRow : 0) * KDIM);

    uint32_t aLd = (uint32_t)((wm + (lane & 15)) * AST + (lane >> 4) * 4) * 4;
    uint32_t bLd = (uint32_t)((wn + ((lane >> 4) & 1) * 8 + (lane & 7)) * AST
                              + ((lane >> 3) & 1) * 4) * 4;

    float c[4][8][4] = {};

    {
        uint32_t as = smB + aOff[0] + (uint32_t)tid * AST * 4;
        #pragma unroll
        for (int s = 0; s < 4; s++) cp16(as + s * 16, aG + s * 16, true);
        uint32_t bs = smB + bOff[0] + (uint32_t)bRow * AST * 4 + bSeg;
        cp16(bs,      bG + bSeg,      bv);
        cp16(bs + 16, bG + bSeg + 16, bv);
        cpcommit();
    }
    const int NCH = KDIM / 32;
    for (int ch = 0; ch < NCH; ch++) {
        int cur = ch & 1;
        if (ch + 1 < NCH) {
            int nb = cur ^ 1;
            uint32_t as = smB + aOff[nb] + (uint32_t)tid * AST * 4;
            const char* ag = aG + (ch + 1) * 64;
            #pragma unroll
            for (int s = 0; s < 4; s++) cp16(as + s * 16, ag + s * 16, true);
            uint32_t bs = smB + bOff[nb] + (uint32_t)bRow * AST * 4 + bSeg;
            cp16(bs,      bG + (ch + 1) * 64 + bSeg,      bv);
            cp16(bs + 16, bG + (ch + 1) * 64 + bSeg + 16, bv);
            cpcommit(); cpwait<1>();
        } else cpwait<0>();
        __syncthreads();
        uint32_t aT = smB + aOff[cur] + aLd;
        uint32_t bT = smB + bOff[cur] + bLd;
        #pragma unroll
        for (int ks = 0; ks < 2; ks++) {
            uint32_t a[4][4], b[8][2];
            #pragma unroll
            for (int mi = 0; mi < 4; mi++)
                ldsm4(a[mi], aT + (uint32_t)(mi * 16 * AST + ks * 8) * 4);
            #pragma unroll
            for (int p = 0; p < 4; p++) {
                uint32_t r[4];
                ldsm4(r, bT + (uint32_t)(p * 16 * AST + ks * 8) * 4);
                b[2 * p][0] = r[0]; b[2 * p][1] = r[1];
                b[2 * p + 1][0] = r[2]; b[2 * p + 1][1] = r[3];
            }
            #pragma unroll
            for (int mi = 0; mi < 4; mi++)
                #pragma unroll
                for (int nj = 0; nj < 8; nj++)
                    mma_bf16(c[mi][nj], a[mi], b[nj]);
        }
        __syncthreads();
    }
    #pragma unroll
    for (int mi = 0; mi < 4; mi++) {
        float s0 = 0.f, s1 = 0.f;
        #pragma unroll
        for (int nj = 0; nj < 8; nj++) {
            int col = nc + wn + nj * 8 + 2 * qid;
            if (col < NHEAD)     { s0 += __expf(c[mi][nj][0]); s1 += __expf(c[mi][nj][2]); }
            if (col + 1 < NHEAD) { s0 += __expf(c[mi][nj][1]); s1 += __expf(c[mi][nj][3]); }
        }
        s0 += __shfl_xor_sync(0xffffffffu, s0, 1);
        s0 += __shfl_xor_sync(0xffffffffu, s0, 2);
        s1 += __shfl_xor_sync(0xffffffffu, s1, 1);
        s1 += __shfl_xor_sync(0xffffffffu, s1, 2);
        if (qid == 0) {
            atomicAdd(&rowAcc[wm + mi * 16 + grp], s0);
            atomicAdd(&rowAcc[wm + mi * 16 + grp + 8], s1);
        }
    }
    __syncthreads();
    atomicAdd(&g_sum_head[row0 + tid], rowAcc[tid]);
}

// ---- TAILS: A resident in smem, B whole-K tiles double-buffered -------------
template<int K, int NBLK, int WHICH>
__global__ void __launch_bounds__(256) expsum_tail() {
    extern __shared__ uint32_t sm[];
    const int ST = K / 2 + 4;
    const int NJ = NBLK / 16;
    const int WN = NBLK / 2;
    float* rowAcc = (float*)(sm + 256 * ST + 2 * NBLK * ST);
    int* rowsId = (int*)(rowAcc + 256);

    int M; const int* idx; const __nv_bfloat16 *A, *B; int ncols;
    if (WHICH == 1) { M = g_cnt0; idx = g_idx0; A = g_proj0h; B = g_emb0h; ncols = SZ0; }
    else            { M = g_cnt1; idx = g_idx1; A = g_proj1h; B = g_emb1h; ncols = SZ1; }

    int row0 = blockIdx.x * 256;
    if (row0 >= M) return;
    int tid = threadIdx.x;
    int rid = row0 + tid; if (rid > M - 1) rid = M - 1;
    int myRow = idx[rid];
    rowsId[tid] = myRow;
    rowAcc[tid] = 0.f;

    uint32_t smB = (uint32_t)__cvta_generic_to_shared(sm);
    const uint32_t bOff[2] = { 256u * ST * 4, (256u + NBLK) * ST * 4 };

    {
        const char* aG = (const char*)(A + (size_t)myRow * K);
        uint32_t as = smB + (uint32_t)tid * ST * 4;
        #pragma unroll
        for (int s = 0; s < K / 8; s++) cp16(as + s * 16, aG + s * 16, true);
    }
    const int TPR = 256 / NBLK;
    const int SEGB = 2 * K / TPR;
    int bRow = tid / TPR, bSeg = (tid % TPR) * SEGB;

    int warp = tid >> 5, lane = tid & 31, grp = lane >> 2, qid = lane & 3;
    int wm = (warp >> 1) * 64, wn = (warp & 1) * WN;

    uint32_t aLd = (uint32_t)((wm + (lane & 15)) * ST + (lane >> 4) * 4) * 4;
    uint32_t bLd = (uint32_t)((wn + ((lane >> 4) & 1) * 8 + (lane & 7)) * ST
                              + ((lane >> 3) & 1) * 4) * 4;

    int ncStride = gridDim.y * NBLK;
    int nc0 = blockIdx.y * NBLK;

    auto loadB = [&](int nc, int buf) {
        int br = nc + bRow;
        bool v = br < ncols;
        const char* bg = (const char*)(B + (size_t)(v ? br : 0) * K) + bSeg;
        uint32_t bs = smB + bOff[buf] + (uint32_t)bRow * ST * 4 + bSeg;
        #pragma unroll
        for (int j = 0; j < SEGB / 16; j++) cp16(bs + j * 16, bg + j * 16, v);
    };
    if (nc0 < ncols) loadB(nc0, 0);
    cpcommit();

    int buf = 0;
    for (int nc = nc0; nc < ncols; nc += ncStride) {
        if (nc + ncStride < ncols) { loadB(nc + ncStride, buf ^ 1); cpcommit(); cpwait<1>(); }
        else cpwait<0>();
        __syncthreads();

        float c[4][NJ][4];
        #pragma unroll
        for (int mi = 0; mi < 4; mi++)
            #pragma unroll
            for (int nj = 0; nj < NJ; nj++)
                #pragma unroll
                for (int r = 0; r < 4; r++) c[mi][nj][r] = 0.f;

        uint32_t aT = smB + aLd;
        uint32_t bT = smB + bOff[buf] + bLd;
        #pragma unroll
        for (int ks = 0; ks < K / 16; ks++) {
            uint32_t a[4][4], b[NJ][2];
            #pragma unroll
            for (int mi = 0; mi < 4; mi++)
                ldsm4(a[mi], aT + (uint32_t)(mi * 16 * ST + ks * 8) * 4);
            #pragma unroll
            for (int p = 0; p < NJ / 2; p++) {
                uint32_t r[4];
                ldsm4(r, bT + (uint32_t)(p * 16 * ST + ks * 8) * 4);
                b[2 * p][0] = r[0]; b[2 * p][1] = r[1];
                b[2 * p + 1][0] = r[2]; b[2 * p + 1][1] = r[3];
            }
            #pragma unroll
            for (int mi = 0; mi < 4; mi++)
                #pragma unroll
                for (int nj = 0; nj < NJ; nj++)
                    mma_bf16(c[mi][nj], a[mi], b[nj]);
        }
        #pragma unroll
        for (int mi = 0; mi < 4; mi++) {
            float s0 = 0.f, s1 = 0.f;
            #pragma unroll
            for (int nj = 0; nj < NJ; nj++) {
                int col = nc + wn + nj * 8 + 2 * qid;
                if (col < ncols)     { s0 += __expf(c[mi][nj][0]); s1 += __expf(c[mi][nj][2]); }
                if (col + 1 < ncols) { s0 += __expf(c[mi][nj][1]); s1 += __expf(c[mi][nj][3]); }
            }
            s0 += __shfl_xor_sync(0xffffffffu, s0, 1);
            s0 += __shfl_xor_sync(0xffffffffu, s0, 2);
            s1 += __shfl_xor_sync(0xffffffffu, s1, 1);
            s1 += __shfl_xor_sync(0xffffffffu, s1, 2);
            if (qid == 0) {
                atomicAdd(&rowAcc[wm + mi * 16 + grp], s0);
                atomicAdd(&rowAcc[wm + mi * 16 + grp + 8], s1);
            }
        }
        __syncthreads();
        buf ^= 1;
    }
    if (row0 + tid < M) atomicAdd(&g_sum_tail[rowsId[tid]], rowAcc[tid]);
}

// ---------------- final gather ----------------------------------------------
__global__ void __launch_bounds__(256) final_kernel(
    const float* __restrict__ inputs, const int* __restrict__ targets,
    const float* __restrict__ head_W, const float* __restrict__ emb0,
    const float* __restrict__ emb1, float* __restrict__ out)
{
    int warp = (blockIdx.x * blockDim.x + threadIdx.x) >> 5;
    int lane = threadIdx.x & 31;
    if (warp >= NROWS) return;
    int row = warp;
    int t = targets[row];
    int ht = (t < CUT0) ? t : ((t < CUT1) ? CUT0 : CUT0 + 1);

    float s = 0.f;
    const float* x = inputs + (long)row * KDIM;
    const float* w = head_W + (long)ht * KDIM;
    for (int k = lane; k < KDIM; k += 32) s += x[k] * w[k];
    #pragma unroll
    for (int o = 16; o; o >>= 1) s += __shfl_xor_sync(0xffffffffu, s, o);
    float res = s - logf(g_sum_head[row]);

    if (t >= CUT0) {
        float tl = 0.f;
        if (t < CUT1) {
            const float* p = g_proj0 + (long)row * D0;
            const float* e = emb0 + (long)(t - CUT0) * D0;
            for (int k = lane; k < D0; k += 32) tl += p[k] * e[k];
        } else {
            const float* p = g_proj1 + (long)row * D1;
            const float* e = emb1 + (long)(t - CUT1) * D1;
            for (int k = lane; k < D1; k += 32) tl += p[k] * e[k];
        }
        #pragma unroll
        for (int o = 16; o; o >>= 1) tl += __shfl_xor_sync(0xffffffffu, tl, o);
        res += tl - logf(g_sum_tail[row]);
    }
    if (lane == 0) out[row] = res;
}

// -------- deterministic double-precision loss reduction ---------------------
__global__ void __launch_bounds__(1024) loss_kernel(float* __restrict__ out, int out_size) {
    __shared__ double sh[1024];
    int tid = threadIdx.x;
    double s = 0.0;
    for (int i = tid; i < NROWS; i += 1024) s += (double)out[i];
    sh[tid] = s;
    __syncthreads();
    for (int o = 512; o; o >>= 1) {
        if (tid < o) sh[tid] += sh[tid + o];
        __syncthreads();
    }
    if (tid == 0 && out_size > NROWS)
        out[out_size - 1] = (float)(-sh[0] / (double)NROWS);
}

// ---------------- launch -----------------------------------------------------
extern "C" void kernel_launch(void* const* d_in, const int* in_sizes, int n_in,
                              void* d_out, int out_size) {
    const float* inputs = 0; const int* targets = 0; const float* head_W = 0;
    const float* emb0 = 0; const float* lin0 = 0; const float* emb1 = 0; const float* lin1 = 0;
    for (int i = 0; i < n_in; i++) {
        switch (in_sizes[i]) {
            case NROWS * KDIM:  inputs  = (const float*)d_in[i]; break;
            case NROWS:         targets = (const int*)  d_in[i]; break;
            case NHEAD * KDIM:  head_W  = (const float*)d_in[i]; break;
            case SZ0 * D0:      emb0    = (const float*)d_in[i]; break;
            case KDIM * D0:     lin0    = (const float*)d_in[i]; break;
            case SZ1 * D1:      emb1    = (const float*)d_in[i]; break;
            case KDIM * D1:     lin1    = (const float*)d_in[i]; break;
        }
    }
    float* out = (float*)d_out;

    const int SMEM_HEAD = (2 * 5120 + 2 * 2560 + 256) * 4;
    const int SMEM_P0   = (2 * 5120 + 2 * 128 * 20) * 4;
    const int SMEM_P1   = (2 * 5120 + 2 * 64 * 20) * 4;
    const int SMEM_T0   = (256 * 132 + 2 * 64 * 132 + 512) * 4;
    const int SMEM_T1   = (256 * 36 + 2 * 128 * 36 + 512) * 4;
    cudaFuncSetAttribute(expsum_head, cudaFuncAttributeMaxDynamicSharedMemorySize, SMEM_HEAD);
    cudaFuncSetAttribute(proj_mma<D0, 128, 0>, cudaFuncAttributeMaxDynamicSharedMemorySize, SMEM_P0);
    cudaFuncSetAttribute(proj_mma<D1, 64, 1>,  cudaFuncAttributeMaxDynamicSharedMemorySize, SMEM_P1);
    cudaFuncSetAttribute(expsum_tail<256, 64, 1>, cudaFuncAttributeMaxDynamicSharedMemorySize, SMEM_T0);
    cudaFuncSetAttribute(expsum_tail<64, 128, 2>, cudaFuncAttributeMaxDynamicSharedMemorySize, SMEM_T1);

    init_kernel<<<16, 256>>>();
    classify_kernel<<<16, 256>>>(targets);
    cvt_all<<<2048, 256>>>(inputs, head_W, emb0, emb1);
    cvt_lin<<<512, 256>>>(lin0, lin1);

    proj_mma<D0, 128, 0><<<dim3(16, 2), 256, SMEM_P0>>>();
    proj_mma<D1, 64, 1><<<dim3(16, 1), 256, SMEM_P1>>>();

    expsum_head<<<dim3(16, 16), 256, SMEM_HEAD>>>();
    expsum_tail<256, 64, 1><<<dim3(16, 63), 256, SMEM_T0>>>();
    expsum_tail<64, 128, 2><<<dim3(16, 20), 256, SMEM_T1>>>();

    final_kernel<<<(NROWS * 32) / 256, 256>>>(inputs, targets, head_W, emb0, emb1, out);
    loss_kernel<<<1, 1024>>>(out, out_size);
}

// round 11
// speedup vs baseline: 2.0543x; 1.1948x over previous
#include <cuda_runtime.h>
#include <cuda_bf16.h>
#include <math.h>
#include <stdint.h>

#define NROWS 4096
#define KDIM  1024
#define NHEAD 2002
#define CUT0  2000
#define CUT1  10000
#define NTOK  50257
#define SZ0   8000
#define SZ1   40257
#define D0    256
#define D1    64

// ---------------- scratch (device globals; no allocation allowed) -----------
// NOTE: counters/sums rely on zero-init at module load; loss_kernel re-zeroes
// them at the END of every replay so each graph replay starts clean.
__device__ float g_proj0[NROWS * D0];
__device__ float g_proj1[NROWS * D1];
__device__ float g_sum_head[NROWS];
__device__ float g_sum_tail[NROWS];
__device__ int   g_idx0[NROWS];
__device__ int   g_idx1[NROWS];
__device__ int   g_cnt0, g_cnt1;

__device__ __align__(16) __nv_bfloat16 g_inh[NROWS * KDIM];
__device__ __align__(16) __nv_bfloat16 g_headWh[NHEAD * KDIM];
__device__ __align__(16) __nv_bfloat16 g_emb0h[SZ0 * D0];
__device__ __align__(16) __nv_bfloat16 g_emb1h[SZ1 * D1];
__device__ __align__(16) __nv_bfloat16 g_proj0h[NROWS * D0];
__device__ __align__(16) __nv_bfloat16 g_proj1h[NROWS * D1];
__device__ __align__(16) __nv_bfloat16 g_lin0t[D0 * KDIM];   // [n][k]
__device__ __align__(16) __nv_bfloat16 g_lin1t[D1 * KDIM];   // [n][k]

// ---------------- helpers ----------------------------------------------------
__device__ __forceinline__ void cp16(uint32_t s, const void* g, bool v) {
    if (v) asm volatile("cp.async.cg.shared.global [%0], [%1], 16;\n" :: "r"(s), "l"(g));
    else   asm volatile("cp.async.cg.shared.global [%0], [%1], 16, 0;\n" :: "r"(s), "l"(g));
}
__device__ __forceinline__ void cpcommit() { asm volatile("cp.async.commit_group;\n"); }
template<int N> __device__ __forceinline__ void cpwait() {
    asm volatile("cp.async.wait_group %0;\n" :: "n"(N));
}
__device__ __forceinline__ void mma_bf16(float c[4], const uint32_t a[4], const uint32_t b[2]) {
    asm volatile(
        "mma.sync.aligned.m16n8k16.row.col.f32.bf16.bf16.f32 "
        "{%0,%1,%2,%3}, {%4,%5,%6,%7}, {%8,%9}, {%0,%1,%2,%3};"
        : "+f"(c[0]), "+f"(c[1]), "+f"(c[2]), "+f"(c[3])
        : "r"(a[0]), "r"(a[1]), "r"(a[2]), "r"(a[3]), "r"(b[0]), "r"(b[1]));
}
__device__ __forceinline__ void ldsm4(uint32_t r[4], uint32_t addr) {
    asm volatile("ldmatrix.sync.aligned.m8n8.x4.shared.b16 {%0,%1,%2,%3}, [%4];"
        : "=r"(r[0]), "=r"(r[1]), "=r"(r[2]), "=r"(r[3]) : "r"(addr));
}

// ---------------- prep: classify + all bf16 conversions ----------------------
__global__ void prep_kernel(const float* __restrict__ i0, const float* __restrict__ i1,
                            const float* __restrict__ i2, const float* __restrict__ i3,
                            const float* __restrict__ lin0, const float* __restrict__ lin1,
                            const int* __restrict__ targets) {
    int t = blockIdx.x * blockDim.x + threadIdx.x;
    int gs = gridDim.x * blockDim.x;
    // classify (counters are pre-zeroed)
    for (int i = t; i < NROWS; i += gs) {
        int tg = targets[i];
        if (tg >= CUT0 && tg < CUT1) { int p = atomicAdd(&g_cnt0, 1); g_idx0[p] = i; }
        else if (tg >= CUT1)         { int p = atomicAdd(&g_cnt1, 1); g_idx1[p] = i; }
    }
    // bf16 conversions (vectorized)
    const float* srcs[4] = { i0, i1, i2, i3 };
    __nv_bfloat16* dsts[4] = { g_inh, g_headWh, g_emb0h, g_emb1h };
    const int n4s[4] = { NROWS * KDIM / 4, NHEAD * KDIM / 4, SZ0 * D0 / 4, SZ1 * D1 / 4 };
    #pragma unroll
    for (int a = 0; a < 4; a++) {
        const float4* s = (const float4*)srcs[a];
        __nv_bfloat162* d = (__nv_bfloat162*)dsts[a];
        for (int i = t; i < n4s[a]; i += gs) {
            float4 v = s[i];
            d[2 * i]     = __floats2bfloat162_rn(v.x, v.y);
            d[2 * i + 1] = __floats2bfloat162_rn(v.z, v.w);
        }
    }
    // lin transposes [k][n] -> [n][k]
    for (int i = t; i < D0 * KDIM; i += gs) {
        int n = i >> 10, k = i & (KDIM - 1);
        g_lin0t[i] = __float2bfloat16(lin0[k * D0 + n]);
    }
    for (int i = t; i < D1 * KDIM; i += gs) {
        int n = i >> 10, k = i & (KDIM - 1);
        g_lin1t[i] = __float2bfloat16(lin1[k * D1 + n]);
    }
}

// ---------------- tensor-core projection (merged, 128-row tiles) -------------
template<int NOUT, int NBLK, int WHICH>
__device__ __forceinline__ void proj_body(uint32_t* sm, int yIdx) {
    const int AST = 20;
    const int NJ = NBLK / 16;
    uint32_t smB = (uint32_t)__cvta_generic_to_shared(sm);
    const uint32_t aOff[2] = { 0u, 2560u * 4 };
    const uint32_t bOff[2] = { 5120u * 4, (5120u + NBLK * AST) * 4 };

    float* __restrict__ P = (WHICH == 0) ? g_proj0 : g_proj1;
    __nv_bfloat16* __restrict__ Ph = (WHICH == 0) ? g_proj0h : g_proj1h;
    const __nv_bfloat16* __restrict__ Bt = (WHICH == 0) ? g_lin0t : g_lin1t;

    int tid = threadIdx.x;
    int row0 = blockIdx.x * 128;
    int nc = yIdx * NBLK;
    int warp = tid >> 5, lane = tid & 31, grp = lane >> 2, qid = lane & 3;
    int wm = (warp >> 1) * 32, wn = (warp & 1) * (NBLK / 2);

    // A: 128 rows, 2 thr/row, 32B each per 64B chunk
    int ar = tid >> 1, aSeg = (tid & 1) * 32;
    const char* aG = (const char*)(g_inh + (size_t)(row0 + ar) * KDIM) + aSeg;
    const int TPR = 256 / NBLK;
    const int SEG = 64 / TPR;
    int bRow = tid / TPR, bSeg = (tid % TPR) * SEG;
    const char* bG = (const char*)(Bt + (size_t)(nc + bRow) * KDIM) + bSeg;

    uint32_t aLd = (uint32_t)((wm + (lane & 15)) * AST + (lane >> 4) * 4) * 4;
    uint32_t bLd = (uint32_t)((wn + ((lane >> 4) & 1) * 8 + (lane & 7)) * AST
                              + ((lane >> 3) & 1) * 4) * 4;

    float c[2][NJ][4];
    #pragma unroll
    for (int mi = 0; mi < 2; mi++)
        #pragma unroll
        for (int nj = 0; nj < NJ; nj++)
            #pragma unroll
            for (int r = 0; r < 4; r++) c[mi][nj][r] = 0.f;

    {   // chunk 0
        uint32_t as = smB + aOff[0] + (uint32_t)(ar * AST) * 4 + aSeg;
        cp16(as, aG, true); cp16(as + 16, aG + 16, true);
        uint32_t bs = smB + bOff[0] + (uint32_t)(bRow * AST) * 4 + bSeg;
        #pragma unroll
        for (int s = 0; s < SEG / 16; s++) cp16(bs + s * 16, bG + s * 16, true);
        cpcommit();
    }
    const int NCH = KDIM / 32;
    for (int ch = 0; ch < NCH; ch++) {
        int cur = ch & 1;
        if (ch + 1 < NCH) {
            int nb = cur ^ 1;
            uint32_t as = smB + aOff[nb] + (uint32_t)(ar * AST) * 4 + aSeg;
            const char* ag = aG + (ch + 1) * 64;
            cp16(as, ag, true); cp16(as + 16, ag + 16, true);
            uint32_t bs = smB + bOff[nb] + (uint32_t)(bRow * AST) * 4 + bSeg;
            const char* bg = bG + (ch + 1) * 64;
            #pragma unroll
            for (int s = 0; s < SEG / 16; s++) cp16(bs + s * 16, bg + s * 16, true);
            cpcommit(); cpwait<1>();
        } else cpwait<0>();
        __syncthreads();
        uint32_t aT = smB + aOff[cur] + aLd;
        uint32_t bT = smB + bOff[cur] + bLd;
        #pragma unroll
        for (int ks = 0; ks < 2; ks++) {
            uint32_t a[2][4], b[NJ][2];
            #pragma unroll
            for (int mi = 0; mi < 2; mi++)
                ldsm4(a[mi], aT + (uint32_t)(mi * 16 * AST + ks * 8) * 4);
            #pragma unroll
            for (int p = 0; p < NJ / 2; p++) {
                uint32_t r[4];
                ldsm4(r, bT + (uint32_t)(p * 16 * AST + ks * 8) * 4);
                b[2 * p][0] = r[0]; b[2 * p][1] = r[1];
                b[2 * p + 1][0] = r[2]; b[2 * p + 1][1] = r[3];
            }
            #pragma unroll
            for (int mi = 0; mi < 2; mi++)
                #pragma unroll
                for (int nj = 0; nj < NJ; nj++)
                    mma_bf16(c[mi][nj], a[mi], b[nj]);
        }
        __syncthreads();
    }
    #pragma unroll
    for (int mi = 0; mi < 2; mi++) {
        #pragma unroll
        for (int nj = 0; nj < NJ; nj++) {
            int r0 = row0 + wm + mi * 16 + grp;
            int col = nc + wn + nj * 8 + 2 * qid;
            long o0 = (long)r0 * NOUT + col;
            long o1 = (long)(r0 + 8) * NOUT + col;
            *reinterpret_cast<float2*>(&P[o0]) = make_float2(c[mi][nj][0], c[mi][nj][1]);
            *reinterpret_cast<float2*>(&P[o1]) = make_float2(c[mi][nj][2], c[mi][nj][3]);
            *reinterpret_cast<__nv_bfloat162*>(&Ph[o0]) =
                __floats2bfloat162_rn(c[mi][nj][0], c[mi][nj][1]);
            *reinterpret_cast<__nv_bfloat162*>(&Ph[o1]) =
                __floats2bfloat162_rn(c[mi][nj][2], c[mi][nj][3]);
        }
    }
}

__global__ void __launch_bounds__(256) proj_all() {
    extern __shared__ uint32_t sm[];
    if (blockIdx.y < 2) proj_body<D0, 128, 0>(sm, blockIdx.y);
    else                proj_body<D1, 64, 1>(sm, 0);
}

// ======================= bf16 tensor-core exp-sum (ldmatrix) =================

// ---- HEAD body: K=1024, k-chunk 32, A+B cp.async double-buffered ------------
__device__ __forceinline__ void head_body(uint32_t* sm, int yIdx) {
    const int AST = 20;
    float* rowAcc = (float*)(sm + 15360);
    uint32_t smB = (uint32_t)__cvta_generic_to_shared(sm);
    const uint32_t aOff[2] = { 0u, 5120u * 4 };
    const uint32_t bOff[2] = { 10240u * 4, 12800u * 4 };

    int tid = threadIdx.x;
    rowAcc[tid] = 0.f;
    int row0 = blockIdx.x * 256;
    int warp = tid >> 5, lane = tid & 31, grp = lane >> 2, qid = lane & 3;
    int wm = (warp >> 1) * 64, wn = (warp & 1) * 64;
    int nc = yIdx * 128;

    const char* aG = (const char*)(g_inh + (size_t)(row0 + tid) * KDIM);
    int bRow = tid >> 1, bSeg = (tid & 1) * 32;
    int bGRow = nc + bRow;
    bool bv = bGRow < NHEAD;
    const char* bG = (const char*)(g_headWh + (size_t)(bv ? bGRow : 0) * KDIM);

    uint32_t aLd = (uint32_t)((wm + (lane & 15)) * AST + (lane >> 4) * 4) * 4;
    uint32_t bLd = (uint32_t)((wn + ((lane >> 4) & 1) * 8 + (lane & 7)) * AST
                              + ((lane >> 3) & 1) * 4) * 4;

    float c[4][8][4] = {};

    {
        uint32_t as = smB + aOff[0] + (uint32_t)tid * AST * 4;
        #pragma unroll
        for (int s = 0; s < 4; s++) cp16(as + s * 16, aG + s * 16, true);
        uint32_t bs = smB + bOff[0] + (uint32_t)bRow * AST * 4 + bSeg;
        cp16(bs,      bG + bSeg,      bv);
        cp16(bs + 16, bG + bSeg + 16, bv);
        cpcommit();
    }
    const int NCH = KDIM / 32;
    for (int ch = 0; ch < NCH; ch++) {
        int cur = ch & 1;
        if (ch + 1 < NCH) {
            int nb = cur ^ 1;
            uint32_t as = smB + aOff[nb] + (uint32_t)tid * AST * 4;
            const char* ag = aG + (ch + 1) * 64;
            #pragma unroll
            for (int s = 0; s < 4; s++) cp16(as + s * 16, ag + s * 16, true);
            uint32_t bs = smB + bOff[nb] + (uint32_t)bRow * AST * 4 + bSeg;
            cp16(bs,      bG + (ch + 1) * 64 + bSeg,      bv);
            cp16(bs + 16, bG + (ch + 1) * 64 + bSeg + 16, bv);
            cpcommit(); cpwait<1>();
        } else cpwait<0>();
        __syncthreads();
        uint32_t aT = smB + aOff[cur] + aLd;
        uint32_t bT = smB + bOff[cur] + bLd;
        #pragma unroll
        for (int ks = 0; ks < 2; ks++) {
            uint32_t a[4][4], b[8][2];
            #pragma unroll
            for (int mi = 0; mi < 4; mi++)
                ldsm4(a[mi], aT + (uint32_t)(mi * 16 * AST + ks * 8) * 4);
            #pragma unroll
            for (int p = 0; p < 4; p++) {
                uint32_t r[4];
                ldsm4(r, bT + (uint32_t)(p * 16 * AST + ks * 8) * 4);
                b[2 * p][0] = r[0]; b[2 * p][1] = r[1];
                b[2 * p + 1][0] = r[2]; b[2 * p + 1][1] = r[3];
            }
            #pragma unroll
            for (int mi = 0; mi < 4; mi++)
                #pragma unroll
                for (int nj = 0; nj < 8; nj++)
                    mma_bf16(c[mi][nj], a[mi], b[nj]);
        }
        __syncthreads();
    }
    #pragma unroll
    for (int mi = 0; mi < 4; mi++) {
        float s0 = 0.f, s1 = 0.f;
        #pragma unroll
        for (int nj = 0; nj < 8; nj++) {
            int col = nc + wn + nj * 8 + 2 * qid;
            if (col < NHEAD)     { s0 += __expf(c[mi][nj][0]); s1 += __expf(c[mi][nj][2]); }
            if (col + 1 < NHEAD) { s0 += __expf(c[mi][nj][1]); s1 += __expf(c[mi][nj][3]); }
        }
        s0 += __shfl_xor_sync(0xffffffffu, s0, 1);
        s0 += __shfl_xor_sync(0xffffffffu, s0, 2);
        s1 += __shfl_xor_sync(0xffffffffu, s1, 1);
        s1 += __shfl_xor_sync(0xffffffffu, s1, 2);
        if (qid == 0) {
            atomicAdd(&rowAcc[wm + mi * 16 + grp], s0);
            atomicAdd(&rowAcc[wm + mi * 16 + grp + 8], s1);
        }
    }
    __syncthreads();
    atomicAdd(&g_sum_head[row0 + tid], rowAcc[tid]);
}

// ---- TAIL body: A resident in smem, B whole-K tiles double-buffered ---------
template<int K, int NBLK, int WHICH, int NUMY>
__device__ __forceinline__ void tail_body(uint32_t* sm, int yIdx) {
    const int ST = K / 2 + 4;
    const int NJ = NBLK / 16;
    const int WN = NBLK / 2;
    float* rowAcc = (float*)(sm + 256 * ST + 2 * NBLK * ST);
    int* rowsId = (int*)(rowAcc + 256);

    int M; const int* idx; const __nv_bfloat16 *A, *B; int ncols;
    if (WHICH == 1) { M = g_cnt0; idx = g_idx0; A = g_proj0h; B = g_emb0h; ncols = SZ0; }
    else            { M = g_cnt1; idx = g_idx1; A = g_proj1h; B = g_emb1h; ncols = SZ1; }

    int row0 = blockIdx.x * 256;
    if (row0 >= M) return;
    int tid = threadIdx.x;
    int rid = row0 + tid; if (rid > M - 1) rid = M - 1;
    int myRow = idx[rid];
    rowsId[tid] = myRow;
    rowAcc[tid] = 0.f;

    uint32_t smB = (uint32_t)__cvta_generic_to_shared(sm);
    const uint32_t bOff[2] = { 256u * ST * 4, (256u + NBLK) * ST * 4 };

    {
        const char* aG = (const char*)(A + (size_t)myRow * K);
        uint32_t as = smB + (uint32_t)tid * ST * 4;
        #pragma unroll
        for (int s = 0; s < K / 8; s++) cp16(as + s * 16, aG + s * 16, true);
    }
    const int TPR = 256 / NBLK;
    const int SEGB = 2 * K / TPR;
    int bRow = tid / TPR, bSeg = (tid % TPR) * SEGB;

    int warp = tid >> 5, lane = tid & 31, grp = lane >> 2, qid = lane & 3;
    int wm = (warp >> 1) * 64, wn = (warp & 1) * WN;

    uint32_t aLd = (uint32_t)((wm + (lane & 15)) * ST + (lane >> 4) * 4) * 4;
    uint32_t bLd = (uint32_t)((wn + ((lane >> 4) & 1) * 8 + (lane & 7)) * ST
                              + ((lane >> 3) & 1) * 4) * 4;

    int ncStride = NUMY * NBLK;
    int nc0 = yIdx * NBLK;

    auto loadB = [&](int nc, int buf) {
        int br = nc + bRow;
        bool v = br < ncols;
        const char* bg = (const char*)(B + (size_t)(v ? br : 0) * K) + bSeg;
        uint32_t bs = smB + bOff[buf] + (uint32_t)bRow * ST * 4 + bSeg;
        #pragma unroll
        for (int j = 0; j < SEGB / 16; j++) cp16(bs + j * 16, bg + j * 16, v);
    };
    if (nc0 < ncols) loadB(nc0, 0);
    cpcommit();

    int buf = 0;
    for (int nc = nc0; nc < ncols; nc += ncStride) {
        if (nc + ncStride < ncols) { loadB(nc + ncStride, buf ^ 1); cpcommit(); cpwait<1>(); }
        else cpwait<0>();
        __syncthreads();

        float c[4][NJ][4];
        #pragma unroll
        for (int mi = 0; mi < 4; mi++)
            #pragma unroll
            for (int nj = 0; nj < NJ; nj++)
                #pragma unroll
                for (int r = 0; r < 4; r++) c[mi][nj][r] = 0.f;

        uint32_t aT = smB + aLd;
        uint32_t bT = smB + bOff[buf] + bLd;
        #pragma unroll
        for (int ks = 0; ks < K / 16; ks++) {
            uint32_t a[4][4], b[NJ][2];
            #pragma unroll
            for (int mi = 0; mi < 4; mi++)
                ldsm4(a[mi], aT + (uint32_t)(mi * 16 * ST + ks * 8) * 4);
            #pragma unroll
            for (int p = 0; p < NJ / 2; p++) {
                uint32_t r[4];
                ldsm4(r, bT + (uint32_t)(p * 16 * ST + ks * 8) * 4);
                b[2 * p][0] = r[0]; b[2 * p][1] = r[1];
                b[2 * p + 1][0] = r[2]; b[2 * p + 1][1] = r[3];
            }
            #pragma unroll
            for (int mi = 0; mi < 4; mi++)
                #pragma unroll
                for (int nj = 0; nj < NJ; nj++)
                    mma_bf16(c[mi][nj], a[mi], b[nj]);
        }
        #pragma unroll
        for (int mi = 0; mi < 4; mi++) {
            float s0 = 0.f, s1 = 0.f;
            #pragma unroll
            for (int nj = 0; nj < NJ; nj++) {
                int col = nc + wn + nj * 8 + 2 * qid;
                if (col < ncols)     { s0 += __expf(c[mi][nj][0]); s1 += __expf(c[mi][nj][2]); }
                if (col + 1 < ncols) { s0 += __expf(c[mi][nj][1]); s1 += __expf(c[mi][nj][3]); }
            }
            s0 += __shfl_xor_sync(0xffffffffu, s0, 1);
            s0 += __shfl_xor_sync(0xffffffffu, s0, 2);
            s1 += __shfl_xor_sync(0xffffffffu, s1, 1);
            s1 += __shfl_xor_sync(0xffffffffu, s1, 2);
            if (qid == 0) {
                atomicAdd(&rowAcc[wm + mi * 16 + grp], s0);
                atomicAdd(&rowAcc[wm + mi * 16 + grp + 8], s1);
            }
        }
        __syncthreads();
        buf ^= 1;
    }
    if (row0 + tid < M) atomicAdd(&g_sum_tail[rowsId[tid]], rowAcc[tid]);
}

// ---- combined expsum: y<16 -> head tile, y>=16 -> tail1 ----------------------
__global__ void __launch_bounds__(256) expsum_main() {
    extern __shared__ uint32_t sm[];
    if (blockIdx.y < 16) head_body(sm, blockIdx.y);
    else                 tail_body<64, 128, 2, 20>(sm, blockIdx.y - 16);
}

// ---- tail0 standalone (K=256, large resident A) ------------------------------
__global__ void __launch_bounds__(256) expsum_tail0() {
    extern __shared__ uint32_t sm[];
    tail_body<256, 64, 1, 63>(sm, blockIdx.y);
}

// ---------------- final gather ----------------------------------------------
__global__ void __launch_bounds__(256) final_kernel(
    const float* __restrict__ inputs, const int* __restrict__ targets,
    const float* __restrict__ head_W, const float* __restrict__ emb0,
    const float* __restrict__ emb1, float* __restrict__ out)
{
    int warp = (blockIdx.x * blockDim.x + threadIdx.x) >> 5;
    int lane = threadIdx.x & 31;
    if (warp >= NROWS) return;
    int row = warp;
    int t = targets[row];
    int ht = (t < CUT0) ? t : ((t < CUT1) ? CUT0 : CUT0 + 1);

    float s = 0.f;
    const float* x = inputs + (long)row * KDIM;
    const float* w = head_W + (long)ht * KDIM;
    for (int k = lane; k < KDIM; k += 32) s += x[k] * w[k];
    #pragma unroll
    for (int o = 16; o; o >>= 1) s += __shfl_xor_sync(0xffffffffu, s, o);
    float res = s - logf(g_sum_head[row]);

    if (t >= CUT0) {
        float tl = 0.f;
        if (t < CUT1) {
            const float* p = g_proj0 + (long)row * D0;
            const float* e = emb0 + (long)(t - CUT0) * D0;
            for (int k = lane; k < D0; k += 32) tl += p[k] * e[k];
        } else {
            const float* p = g_proj1 + (long)row * D1;
            const float* e = emb1 + (long)(t - CUT1) * D1;
            for (int k = lane; k < D1; k += 32) tl += p[k] * e[k];
        }
        #pragma unroll
        for (int o = 16; o; o >>= 1) tl += __shfl_xor_sync(0xffffffffu, tl, o);
        res += tl - logf(g_sum_tail[row]);
    }
    if (lane == 0) out[row] = res;
}

// -------- loss reduction (double) + state reset for next replay ---------------
__global__ void __launch_bounds__(1024) loss_kernel(float* __restrict__ out, int out_size) {
    __shared__ double sh[1024];
    int tid = threadIdx.x;
    double s = 0.0;
    for (int i = tid; i < NROWS; i += 1024) s += (double)out[i];
    sh[tid] = s;
    __syncthreads();
    for (int o = 512; o; o >>= 1) {
        if (tid < o) sh[tid] += sh[tid + o];
        __syncthreads();
    }
    if (tid == 0 && out_size > NROWS)
        out[out_size - 1] = (float)(-sh[0] / (double)NROWS);
    // reset per-replay state (counters/sums must be zero at next replay start)
    for (int i = tid; i < NROWS; i += 1024) { g_sum_head[i] = 0.f; g_sum_tail[i] = 0.f; }
    if (tid == 0) { g_cnt0 = 0; g_cnt1 = 0; }
}

// ---------------- launch -----------------------------------------------------
extern "C" void kernel_launch(void* const* d_in, const int* in_sizes, int n_in,
                              void* d_out, int out_size) {
    const float* inputs = 0; const int* targets = 0; const float* head_W = 0;
    const float* emb0 = 0; const float* lin0 = 0; const float* emb1 = 0; const float* lin1 = 0;
    for (int i = 0; i < n_in; i++) {
        switch (in_sizes[i]) {
            case NROWS * KDIM:  inputs  = (const float*)d_in[i]; break;
            case NROWS:         targets = (const int*)  d_in[i]; break;
            case NHEAD * KDIM:  head_W  = (const float*)d_in[i]; break;
            case SZ0 * D0:      emb0    = (const float*)d_in[i]; break;
            case KDIM * D0:     lin0    = (const float*)d_in[i]; break;
            case SZ1 * D1:      emb1    = (const float*)d_in[i]; break;
            case KDIM * D1:     lin1    = (const float*)d_in[i]; break;
        }
    }
    float* out = (float*)d_out;

    const int SMEM_PROJ = (2 * 2560 + 2 * 128 * 20) * 4;                 // 40 KB
    const int SMEM_MAIN = (256 * 36 + 2 * 128 * 36 + 512) * 4;           // 75.8 KB
    const int SMEM_T0   = (256 * 132 + 2 * 64 * 132 + 512) * 4;          // 203 KB
    cudaFuncSetAttribute(proj_all,     cudaFuncAttributeMaxDynamicSharedMemorySize, SMEM_PROJ);
    cudaFuncSetAttribute(expsum_main,  cudaFuncAttributeMaxDynamicSharedMemorySize, SMEM_MAIN);
    cudaFuncSetAttribute(expsum_tail0, cudaFuncAttributeMaxDynamicSharedMemorySize, SMEM_T0);

    prep_kernel<<<2048, 256>>>(inputs, head_W, emb0, emb1, lin0, lin1, targets);
    proj_all<<<dim3(32, 3), 256, SMEM_PROJ>>>();
    expsum_tail0<<<dim3(16, 63), 256, SMEM_T0>>>();
    expsum_main<<<dim3(16, 36), 256, SMEM_MAIN>>>();
    final_kernel<<<(NROWS * 32) / 256, 256>>>(inputs, targets, head_W, emb0, emb1, out);
    loss_kernel<<<1, 1024>>>(out, out_size);
}

// round 12
// speedup vs baseline: 2.3898x; 1.1633x over previous
#include <cuda_runtime.h>
#include <cuda_bf16.h>
#include <math.h>
#include <stdint.h>

#define NROWS 4096
#define KDIM  1024
#define NHEAD 2002
#define CUT0  2000
#define CUT1  10000
#define NTOK  50257
#define SZ0   8000
#define SZ1   40257
#define D0    256
#define D1    64

// ---------------- scratch (device globals; no allocation allowed) -----------
// Counters/sums zero at module load; loss_kernel re-zeroes at END of each
// replay so every graph replay starts clean.
__device__ float g_proj0[NROWS * D0];
__device__ float g_proj1[NROWS * D1];
__device__ float g_sum_head[NROWS];
__device__ float g_sum_tail[NROWS];
__device__ int   g_idx0[NROWS];
__device__ int   g_idx1[NROWS];
__device__ int   g_cnt0, g_cnt1;

__device__ __align__(16) __nv_bfloat16 g_inh[NROWS * KDIM];
__device__ __align__(16) __nv_bfloat16 g_headWh[NHEAD * KDIM];
__device__ __align__(16) __nv_bfloat16 g_emb0h[SZ0 * D0];
__device__ __align__(16) __nv_bfloat16 g_emb1h[SZ1 * D1];
__device__ __align__(16) __nv_bfloat16 g_proj0h[NROWS * D0];
__device__ __align__(16) __nv_bfloat16 g_proj1h[NROWS * D1];
__device__ __align__(16) __nv_bfloat16 g_lin0t[D0 * KDIM];   // [n][k]
__device__ __align__(16) __nv_bfloat16 g_lin1t[D1 * KDIM];   // [n][k]

// ---------------- helpers ----------------------------------------------------
__device__ __forceinline__ void cp16(uint32_t s, const void* g, bool v) {
    if (v) asm volatile("cp.async.cg.shared.global [%0], [%1], 16;\n" :: "r"(s), "l"(g));
    else   asm volatile("cp.async.cg.shared.global [%0], [%1], 16, 0;\n" :: "r"(s), "l"(g));
}
__device__ __forceinline__ void cpcommit() { asm volatile("cp.async.commit_group;\n"); }
template<int N> __device__ __forceinline__ void cpwait() {
    asm volatile("cp.async.wait_group %0;\n" :: "n"(N));
}
__device__ __forceinline__ void mma_bf16(float c[4], const uint32_t a[4], const uint32_t b[2]) {
    asm volatile(
        "mma.sync.aligned.m16n8k16.row.col.f32.bf16.bf16.f32 "
        "{%0,%1,%2,%3}, {%4,%5,%6,%7}, {%8,%9}, {%0,%1,%2,%3};"
        : "+f"(c[0]), "+f"(c[1]), "+f"(c[2]), "+f"(c[3])
        : "r"(a[0]), "r"(a[1]), "r"(a[2]), "r"(a[3]), "r"(b[0]), "r"(b[1]));
}
__device__ __forceinline__ void ldsm4(uint32_t r[4], uint32_t addr) {
    asm volatile("ldmatrix.sync.aligned.m8n8.x4.shared.b16 {%0,%1,%2,%3}, [%4];"
        : "=r"(r[0]), "=r"(r[1]), "=r"(r[2]), "=r"(r[3]) : "r"(addr));
}

// ---------------- prep: classify + all bf16 conversions ----------------------
__global__ void prep_kernel(const float* __restrict__ i0, const float* __restrict__ i1,
                            const float* __restrict__ i2, const float* __restrict__ i3,
                            const float* __restrict__ lin0, const float* __restrict__ lin1,
                            const int* __restrict__ targets) {
    int t = blockIdx.x * blockDim.x + threadIdx.x;
    int gs = gridDim.x * blockDim.x;
    for (int i = t; i < NROWS; i += gs) {
        int tg = targets[i];
        if (tg >= CUT0 && tg < CUT1) { int p = atomicAdd(&g_cnt0, 1); g_idx0[p] = i; }
        else if (tg >= CUT1)         { int p = atomicAdd(&g_cnt1, 1); g_idx1[p] = i; }
    }
    const float* srcs[4] = { i0, i1, i2, i3 };
    __nv_bfloat16* dsts[4] = { g_inh, g_headWh, g_emb0h, g_emb1h };
    const int n4s[4] = { NROWS * KDIM / 4, NHEAD * KDIM / 4, SZ0 * D0 / 4, SZ1 * D1 / 4 };
    #pragma unroll
    for (int a = 0; a < 4; a++) {
        const float4* s = (const float4*)srcs[a];
        __nv_bfloat162* d = (__nv_bfloat162*)dsts[a];
        for (int i = t; i < n4s[a]; i += gs) {
            float4 v = s[i];
            d[2 * i]     = __floats2bfloat162_rn(v.x, v.y);
            d[2 * i + 1] = __floats2bfloat162_rn(v.z, v.w);
        }
    }
    for (int i = t; i < D0 * KDIM; i += gs) {
        int n = i >> 10, k = i & (KDIM - 1);
        g_lin0t[i] = __float2bfloat16(lin0[k * D0 + n]);
    }
    for (int i = t; i < D1 * KDIM; i += gs) {
        int n = i >> 10, k = i & (KDIM - 1);
        g_lin1t[i] = __float2bfloat16(lin1[k * D1 + n]);
    }
}

// ---------------- tensor-core projection (merged, 128-row tiles) -------------
template<int NOUT, int NBLK, int WHICH>
__device__ __forceinline__ void proj_body(uint32_t* sm, int yIdx) {
    const int AST = 20;
    const int NJ = NBLK / 16;
    uint32_t smB = (uint32_t)__cvta_generic_to_shared(sm);
    const uint32_t aOff[2] = { 0u, 2560u * 4 };
    const uint32_t bOff[2] = { 5120u * 4, (5120u + NBLK * AST) * 4 };

    float* __restrict__ P = (WHICH == 0) ? g_proj0 : g_proj1;
    __nv_bfloat16* __restrict__ Ph = (WHICH == 0) ? g_proj0h : g_proj1h;
    const __nv_bfloat16* __restrict__ Bt = (WHICH == 0) ? g_lin0t : g_lin1t;

    int tid = threadIdx.x;
    int row0 = blockIdx.x * 128;
    int nc = yIdx * NBLK;
    int warp = tid >> 5, lane = tid & 31, grp = lane >> 2, qid = lane & 3;
    int wm = (warp >> 1) * 32, wn = (warp & 1) * (NBLK / 2);

    int ar = tid >> 1, aSeg = (tid & 1) * 32;
    const char* aG = (const char*)(g_inh + (size_t)(row0 + ar) * KDIM) + aSeg;
    const int TPR = 256 / NBLK;
    const int SEG = 64 / TPR;
    int bRow = tid / TPR, bSeg = (tid % TPR) * SEG;
    const char* bG = (const char*)(Bt + (size_t)(nc + bRow) * KDIM) + bSeg;

    uint32_t aLd = (uint32_t)((wm + (lane & 15)) * AST + (lane >> 4) * 4) * 4;
    uint32_t bLd = (uint32_t)((wn + ((lane >> 4) & 1) * 8 + (lane & 7)) * AST
                              + ((lane >> 3) & 1) * 4) * 4;

    float c[2][NJ][4];
    #pragma unroll
    for (int mi = 0; mi < 2; mi++)
        #pragma unroll
        for (int nj = 0; nj < NJ; nj++)
            #pragma unroll
            for (int r = 0; r < 4; r++) c[mi][nj][r] = 0.f;

    {
        uint32_t as = smB + aOff[0] + (uint32_t)(ar * AST) * 4 + aSeg;
        cp16(as, aG, true); cp16(as + 16, aG + 16, true);
        uint32_t bs = smB + bOff[0] + (uint32_t)(bRow * AST) * 4 + bSeg;
        #pragma unroll
        for (int s = 0; s < SEG / 16; s++) cp16(bs + s * 16, bG + s * 16, true);
        cpcommit();
    }
    const int NCH = KDIM / 32;
    for (int ch = 0; ch < NCH; ch++) {
        int cur = ch & 1;
        if (ch + 1 < NCH) {
            int nb = cur ^ 1;
            uint32_t as = smB + aOff[nb] + (uint32_t)(ar * AST) * 4 + aSeg;
            const char* ag = aG + (ch + 1) * 64;
            cp16(as, ag, true); cp16(as + 16, ag + 16, true);
            uint32_t bs = smB + bOff[nb] + (uint32_t)(bRow * AST) * 4 + bSeg;
            const char* bg = bG + (ch + 1) * 64;
            #pragma unroll
            for (int s = 0; s < SEG / 16; s++) cp16(bs + s * 16, bg + s * 16, true);
            cpcommit(); cpwait<1>();
        } else cpwait<0>();
        __syncthreads();
        uint32_t aT = smB + aOff[cur] + aLd;
        uint32_t bT = smB + bOff[cur] + bLd;
        #pragma unroll
        for (int ks = 0; ks < 2; ks++) {
            uint32_t a[2][4], b[NJ][2];
            #pragma unroll
            for (int mi = 0; mi < 2; mi++)
                ldsm4(a[mi], aT + (uint32_t)(mi * 16 * AST + ks * 8) * 4);
            #pragma unroll
            for (int p = 0; p < NJ / 2; p++) {
                uint32_t r[4];
                ldsm4(r, bT + (uint32_t)(p * 16 * AST + ks * 8) * 4);
                b[2 * p][0] = r[0]; b[2 * p][1] = r[1];
                b[2 * p + 1][0] = r[2]; b[2 * p + 1][1] = r[3];
            }
            #pragma unroll
            for (int mi = 0; mi < 2; mi++)
                #pragma unroll
                for (int nj = 0; nj < NJ; nj++)
                    mma_bf16(c[mi][nj], a[mi], b[nj]);
        }
        __syncthreads();
    }
    #pragma unroll
    for (int mi = 0; mi < 2; mi++) {
        #pragma unroll
        for (int nj = 0; nj < NJ; nj++) {
            int r0 = row0 + wm + mi * 16 + grp;
            int col = nc + wn + nj * 8 + 2 * qid;
            long o0 = (long)r0 * NOUT + col;
            long o1 = (long)(r0 + 8) * NOUT + col;
            *reinterpret_cast<float2*>(&P[o0]) = make_float2(c[mi][nj][0], c[mi][nj][1]);
            *reinterpret_cast<float2*>(&P[o1]) = make_float2(c[mi][nj][2], c[mi][nj][3]);
            *reinterpret_cast<__nv_bfloat162*>(&Ph[o0]) =
                __floats2bfloat162_rn(c[mi][nj][0], c[mi][nj][1]);
            *reinterpret_cast<__nv_bfloat162*>(&Ph[o1]) =
                __floats2bfloat162_rn(c[mi][nj][2], c[mi][nj][3]);
        }
    }
}

__global__ void __launch_bounds__(256) proj_all() {
    extern __shared__ uint32_t sm[];
    if (blockIdx.y < 2) proj_body<D0, 128, 0>(sm, blockIdx.y);
    else                proj_body<D1, 64, 1>(sm, 0);
}

// =============== merged bf16 exp-sum, warp tile m64n32, 2 CTA/SM =============
// smem layout (u32):
//   chunked: A[2][5120] | B[2][1280] | rowAcc[256]          (13056 u32)
//   resident: A[256*36=9216] | B[2][64*36=2304] | rowAcc     (14080 u32)
#define SM_EXP_U32 14336

// ---- chunked body (head: MODE 0, tail0: MODE 1); N-tile=64, k-chunk 32 ------
template<int K, int MODE>
__device__ __forceinline__ void chunked_body(uint32_t* sm, int yIdx) {
    const int AST = 20;
    float* rowAcc = (float*)(sm + 12800);
    uint32_t smB = (uint32_t)__cvta_generic_to_shared(sm);
    const uint32_t aOff[2] = { 0u, 5120u * 4 };
    const uint32_t bOff[2] = { 10240u * 4, 11520u * 4 };

    int M, ncols;
    const __nv_bfloat16 *Asrc, *Bsrc;
    float* sums;
    if (MODE == 0) { M = NROWS; ncols = NHEAD; Asrc = g_inh;    Bsrc = g_headWh; sums = g_sum_head; }
    else           { M = g_cnt0; ncols = SZ0;  Asrc = g_proj0h; Bsrc = g_emb0h;  sums = g_sum_tail; }

    int row0 = blockIdx.x * 256;
    if (row0 >= M) return;
    int tid = threadIdx.x;
    int rid = row0 + tid; if (rid > M - 1) rid = M - 1;
    int myRow = (MODE == 0) ? rid : g_idx0[rid];
    rowAcc[tid] = 0.f;

    int warp = tid >> 5, lane = tid & 31, grp = lane >> 2, qid = lane & 3;
    int wm = (warp >> 1) * 64, wn = (warp & 1) * 32;
    int nc = yIdx * 64;

    const char* aG = (const char*)(Asrc + (size_t)myRow * K);
    int bRow = tid >> 2, bSeg = (tid & 3) * 16;
    int bGRow = nc + bRow;
    bool bv = bGRow < ncols;
    const char* bG = (const char*)(Bsrc + (size_t)(bv ? bGRow : 0) * K);

    uint32_t aLd = (uint32_t)((wm + (lane & 15)) * AST + (lane >> 4) * 4) * 4;
    uint32_t bLd = (uint32_t)((wn + ((lane >> 4) & 1) * 8 + (lane & 7)) * AST
                              + ((lane >> 3) & 1) * 4) * 4;

    float c[4][4][4];
    #pragma unroll
    for (int mi = 0; mi < 4; mi++)
        #pragma unroll
        for (int nj = 0; nj < 4; nj++)
            #pragma unroll
            for (int r = 0; r < 4; r++) c[mi][nj][r] = 0.f;

    {
        uint32_t as = smB + aOff[0] + (uint32_t)tid * AST * 4;
        #pragma unroll
        for (int s = 0; s < 4; s++) cp16(as + s * 16, aG + s * 16, true);
        cp16(smB + bOff[0] + (uint32_t)bRow * AST * 4 + bSeg, bG + bSeg, bv);
        cpcommit();
    }
    const int NCH = K / 32;
    for (int ch = 0; ch < NCH; ch++) {
        int cur = ch & 1;
        if (ch + 1 < NCH) {
            int nb = cur ^ 1;
            uint32_t as = smB + aOff[nb] + (uint32_t)tid * AST * 4;
            const char* ag = aG + (ch + 1) * 64;
            #pragma unroll
            for (int s = 0; s < 4; s++) cp16(as + s * 16, ag + s * 16, true);
            cp16(smB + bOff[nb] + (uint32_t)bRow * AST * 4 + bSeg,
                 bG + (ch + 1) * 64 + bSeg, bv);
            cpcommit(); cpwait<1>();
        } else cpwait<0>();
        __syncthreads();
        uint32_t aT = smB + aOff[cur] + aLd;
        uint32_t bT = smB + bOff[cur] + bLd;
        #pragma unroll
        for (int ks = 0; ks < 2; ks++) {
            uint32_t a[4][4], b[4][2];
            #pragma unroll
            for (int mi = 0; mi < 4; mi++)
                ldsm4(a[mi], aT + (uint32_t)(mi * 16 * AST + ks * 8) * 4);
            #pragma unroll
            for (int p = 0; p < 2; p++) {
                uint32_t r[4];
                ldsm4(r, bT + (uint32_t)(p * 16 * AST + ks * 8) * 4);
                b[2 * p][0] = r[0]; b[2 * p][1] = r[1];
                b[2 * p + 1][0] = r[2]; b[2 * p + 1][1] = r[3];
            }
            #pragma unroll
            for (int mi = 0; mi < 4; mi++)
                #pragma unroll
                for (int nj = 0; nj < 4; nj++)
                    mma_bf16(c[mi][nj], a[mi], b[nj]);
        }
        __syncthreads();
    }
    #pragma unroll
    for (int mi = 0; mi < 4; mi++) {
        float s0 = 0.f, s1 = 0.f;
        #pragma unroll
        for (int nj = 0; nj < 4; nj++) {
            int col = nc + wn + nj * 8 + 2 * qid;
            if (col < ncols)     { s0 += __expf(c[mi][nj][0]); s1 += __expf(c[mi][nj][2]); }
            if (col + 1 < ncols) { s0 += __expf(c[mi][nj][1]); s1 += __expf(c[mi][nj][3]); }
        }
        s0 += __shfl_xor_sync(0xffffffffu, s0, 1);
        s0 += __shfl_xor_sync(0xffffffffu, s0, 2);
        s1 += __shfl_xor_sync(0xffffffffu, s1, 1);
        s1 += __shfl_xor_sync(0xffffffffu, s1, 2);
        if (qid == 0) {
            atomicAdd(&rowAcc[wm + mi * 16 + grp], s0);
            atomicAdd(&rowAcc[wm + mi * 16 + grp + 8], s1);
        }
    }
    __syncthreads();
    if (row0 + tid < M) atomicAdd(&sums[myRow], rowAcc[tid]);
}

// ---- tail1 resident body: K=64, A in smem once, B tiles double-buffered -----
template<int NUMY>
__device__ __forceinline__ void tail1_body(uint32_t* sm, int yIdx) {
    const int K = 64, ST = 36;
    float* rowAcc = (float*)(sm + 9216 + 4608);
    uint32_t smB = (uint32_t)__cvta_generic_to_shared(sm);
    const uint32_t bOff[2] = { 9216u * 4, (9216u + 2304u) * 4 };

    int M = g_cnt1;
    int ncols = SZ1;
    int row0 = blockIdx.x * 256;
    if (row0 >= M) return;
    int tid = threadIdx.x;
    int rid = row0 + tid; if (rid > M - 1) rid = M - 1;
    int myRow = g_idx1[rid];
    rowAcc[tid] = 0.f;

    {
        const char* aG = (const char*)(g_proj1h + (size_t)myRow * K);
        uint32_t as = smB + (uint32_t)tid * ST * 4;
        #pragma unroll
        for (int s = 0; s < 8; s++) cp16(as + s * 16, aG + s * 16, true);
    }
    int bRow = tid >> 2, bSeg = (tid & 3) * 32;
    int warp = tid >> 5, lane = tid & 31, grp = lane >> 2, qid = lane & 3;
    int wm = (warp >> 1) * 64, wn = (warp & 1) * 32;

    uint32_t aLd = (uint32_t)((wm + (lane & 15)) * ST + (lane >> 4) * 4) * 4;
    uint32_t bLd = (uint32_t)((wn + ((lane >> 4) & 1) * 8 + (lane & 7)) * ST
                              + ((lane >> 3) & 1) * 4) * 4;

    int ncStride = NUMY * 64;
    int nc0 = yIdx * 64;

    auto loadB = [&](int nc, int buf) {
        int br = nc + bRow;
        bool v = br < ncols;
        const char* bg = (const char*)(g_emb1h + (size_t)(v ? br : 0) * K) + bSeg;
        uint32_t bs = smB + bOff[buf] + (uint32_t)bRow * ST * 4 + bSeg;
        cp16(bs, bg, v); cp16(bs + 16, bg + 16, v);
    };
    if (nc0 < ncols) loadB(nc0, 0);
    cpcommit();

    int buf = 0;
    for (int nc = nc0; nc < ncols; nc += ncStride) {
        if (nc + ncStride < ncols) { loadB(nc + ncStride, buf ^ 1); cpcommit(); cpwait<1>(); }
        else cpwait<0>();
        __syncthreads();

        float c[4][4][4];
        #pragma unroll
        for (int mi = 0; mi < 4; mi++)
            #pragma unroll
            for (int nj = 0; nj < 4; nj++)
                #pragma unroll
                for (int r = 0; r < 4; r++) c[mi][nj][r] = 0.f;

        uint32_t aT = smB + aLd;
        uint32_t bT = smB + bOff[buf] + bLd;
        #pragma unroll
        for (int ks = 0; ks < 4; ks++) {
            uint32_t a[4][4], b[4][2];
            #pragma unroll
            for (int mi = 0; mi < 4; mi++)
                ldsm4(a[mi], aT + (uint32_t)(mi * 16 * ST + ks * 8) * 4);
            #pragma unroll
            for (int p = 0; p < 2; p++) {
                uint32_t r[4];
                ldsm4(r, bT + (uint32_t)(p * 16 * ST + ks * 8) * 4);
                b[2 * p][0] = r[0]; b[2 * p][1] = r[1];
                b[2 * p + 1][0] = r[2]; b[2 * p + 1][1] = r[3];
            }
            #pragma unroll
            for (int mi = 0; mi < 4; mi++)
                #pragma unroll
                for (int nj = 0; nj < 4; nj++)
                    mma_bf16(c[mi][nj], a[mi], b[nj]);
        }
        #pragma unroll
        for (int mi = 0; mi < 4; mi++) {
            float s0 = 0.f, s1 = 0.f;
            #pragma unroll
            for (int nj = 0; nj < 4; nj++) {
                int col = nc + wn + nj * 8 + 2 * qid;
                if (col < ncols)     { s0 += __expf(c[mi][nj][0]); s1 += __expf(c[mi][nj][2]); }
                if (col + 1 < ncols) { s0 += __expf(c[mi][nj][1]); s1 += __expf(c[mi][nj][3]); }
            }
            s0 += __shfl_xor_sync(0xffffffffu, s0, 1);
            s0 += __shfl_xor_sync(0xffffffffu, s0, 2);
            s1 += __shfl_xor_sync(0xffffffffu, s1, 1);
            s1 += __shfl_xor_sync(0xffffffffu, s1, 2);
            if (qid == 0) {
                atomicAdd(&rowAcc[wm + mi * 16 + grp], s0);
                atomicAdd(&rowAcc[wm + mi * 16 + grp + 8], s1);
            }
        }
        __syncthreads();
        buf ^= 1;
    }
    if (row0 + tid < M) atomicAdd(&g_sum_tail[myRow], rowAcc[tid]);
}

// y-map: [0,32) head tiles | [32,72) tail1 partitions | [72,197) tail0 tiles
__global__ void __launch_bounds__(256, 2) expsum_all() {
    extern __shared__ uint32_t sm[];
    if (blockIdx.y < 32)      chunked_body<KDIM, 0>(sm, blockIdx.y);
    else if (blockIdx.y < 72) tail1_body<40>(sm, blockIdx.y - 32);
    else                      chunked_body<D0, 1>(sm, blockIdx.y - 72);
}

// ---------------- final gather ----------------------------------------------
__global__ void __launch_bounds__(256) final_kernel(
    const float* __restrict__ inputs, const int* __restrict__ targets,
    const float* __restrict__ head_W, const float* __restrict__ emb0,
    const float* __restrict__ emb1, float* __restrict__ out)
{
    int warp = (blockIdx.x * blockDim.x + threadIdx.x) >> 5;
    int lane = threadIdx.x & 31;
    if (warp >= NROWS) return;
    int row = warp;
    int t = targets[row];
    int ht = (t < CUT0) ? t : ((t < CUT1) ? CUT0 : CUT0 + 1);

    float s = 0.f;
    const float* x = inputs + (long)row * KDIM;
    const float* w = head_W + (long)ht * KDIM;
    for (int k = lane; k < KDIM; k += 32) s += x[k] * w[k];
    #pragma unroll
    for (int o = 16; o; o >>= 1) s += __shfl_xor_sync(0xffffffffu, s, o);
    float res = s - logf(g_sum_head[row]);

    if (t >= CUT0) {
        float tl = 0.f;
        if (t < CUT1) {
            const float* p = g_proj0 + (long)row * D0;
            const float* e = emb0 + (long)(t - CUT0) * D0;
            for (int k = lane; k < D0; k += 32) tl += p[k] * e[k];
        } else {
            const float* p = g_proj1 + (long)row * D1;
            const float* e = emb1 + (long)(t - CUT1) * D1;
            for (int k = lane; k < D1; k += 32) tl += p[k] * e[k];
        }
        #pragma unroll
        for (int o = 16; o; o >>= 1) tl += __shfl_xor_sync(0xffffffffu, tl, o);
        res += tl - logf(g_sum_tail[row]);
    }
    if (lane == 0) out[row] = res;
}

// -------- loss reduction (double) + state reset for next replay ---------------
__global__ void __launch_bounds__(1024) loss_kernel(float* __restrict__ out, int out_size) {
    __shared__ double sh[1024];
    int tid = threadIdx.x;
    double s = 0.0;
    for (int i = tid; i < NROWS; i += 1024) s += (double)out[i];
    sh[tid] = s;
    __syncthreads();
    for (int o = 512; o; o >>= 1) {
        if (tid < o) sh[tid] += sh[tid + o];
        __syncthreads();
    }
    if (tid == 0 && out_size > NROWS)
        out[out_size - 1] = (float)(-sh[0] / (double)NROWS);
    for (int i = tid; i < NROWS; i += 1024) { g_sum_head[i] = 0.f; g_sum_tail[i] = 0.f; }
    if (tid == 0) { g_cnt0 = 0; g_cnt1 = 0; }
}

// ---------------- launch -----------------------------------------------------
extern "C" void kernel_launch(void* const* d_in, const int* in_sizes, int n_in,
                              void* d_out, int out_size) {
    const float* inputs = 0; const int* targets = 0; const float* head_W = 0;
    const float* emb0 = 0; const float* lin0 = 0; const float* emb1 = 0; const float* lin1 = 0;
    for (int i = 0; i < n_in; i++) {
        switch (in_sizes[i]) {
            case NROWS * KDIM:  inputs  = (const float*)d_in[i]; break;
            case NROWS:         targets = (const int*)  d_in[i]; break;
            case NHEAD * KDIM:  head_W  = (const float*)d_in[i]; break;
            case SZ0 * D0:      emb0    = (const float*)d_in[i]; break;
            case KDIM * D0:     lin0    = (const float*)d_in[i]; break;
            case SZ1 * D1:      emb1    = (const float*)d_in[i]; break;
            case KDIM * D1:     lin1    = (const float*)d_in[i]; break;
        }
    }
    float* out = (float*)d_out;

    const int SMEM_PROJ = (2 * 2560 + 2 * 128 * 20) * 4;    // 40 KB
    const int SMEM_EXP  = SM_EXP_U32 * 4;                   // 57.3 KB (2 CTA/SM)
    cudaFuncSetAttribute(proj_all,   cudaFuncAttributeMaxDynamicSharedMemorySize, SMEM_PROJ);
    cudaFuncSetAttribute(expsum_all, cudaFuncAttributeMaxDynamicSharedMemorySize, SMEM_EXP);

    prep_kernel<<<2048, 256>>>(inputs, head_W, emb0, emb1, lin0, lin1, targets);
    proj_all<<<dim3(32, 3), 256, SMEM_PROJ>>>();
    expsum_all<<<dim3(16, 197), 256, SMEM_EXP>>>();
    final_kernel<<<(NROWS * 32) / 256, 256>>>(inputs, targets, head_W, emb0, emb1, out);
    loss_kernel<<<1, 1024>>>(out, out_size);
}

// round 14
// speedup vs baseline: 2.4042x; 1.0061x over previous
#include <cuda_runtime.h>
#include <cuda_bf16.h>
#include <math.h>
#include <stdint.h>

#define NROWS 4096
#define KDIM  1024
#define NHEAD 2002
#define CUT0  2000
#define CUT1  10000
#define NTOK  50257
#define SZ0   8000
#define SZ1   40257
#define D0    256
#define D1    64

// ---------------- scratch (device globals; no allocation allowed) -----------
// Counters/sums zero at module load; loss_kernel re-zeroes at END of each
// replay so every graph replay starts clean.
__device__ float g_proj0[NROWS * D0];
__device__ float g_proj1[NROWS * D1];
__device__ float g_sum_head[NROWS];
__device__ float g_sum_tail[NROWS];
__device__ int   g_idx0[NROWS];
__device__ int   g_idx1[NROWS];
__device__ int   g_cnt0, g_cnt1;

__device__ __align__(16) __nv_bfloat16 g_inh[NROWS * KDIM];
__device__ __align__(16) __nv_bfloat16 g_headWh[NHEAD * KDIM];
__device__ __align__(16) __nv_bfloat16 g_emb0h[SZ0 * D0];
__device__ __align__(16) __nv_bfloat16 g_emb1h[SZ1 * D1];
__device__ __align__(16) __nv_bfloat16 g_proj0h[NROWS * D0];
__device__ __align__(16) __nv_bfloat16 g_proj1h[NROWS * D1];
__device__ __align__(16) __nv_bfloat16 g_lin0t[D0 * KDIM];   // [n][k]
__device__ __align__(16) __nv_bfloat16 g_lin1t[D1 * KDIM];   // [n][k]

// ---------------- helpers ----------------------------------------------------
__device__ __forceinline__ void cp16(uint32_t s, const void* g, bool v) {
    if (v) asm volatile("cp.async.cg.shared.global [%0], [%1], 16;\n" :: "r"(s), "l"(g));
    else   asm volatile("cp.async.cg.shared.global [%0], [%1], 16, 0;\n" :: "r"(s), "l"(g));
}
__device__ __forceinline__ void cpcommit() { asm volatile("cp.async.commit_group;\n"); }
template<int N> __device__ __forceinline__ void cpwait() {
    asm volatile("cp.async.wait_group %0;\n" :: "n"(N));
}
__device__ __forceinline__ void mma_bf16(float c[4], const uint32_t a[4], const uint32_t b[2]) {
    asm volatile(
        "mma.sync.aligned.m16n8k16.row.col.f32.bf16.bf16.f32 "
        "{%0,%1,%2,%3}, {%4,%5,%6,%7}, {%8,%9}, {%0,%1,%2,%3};"
        : "+f"(c[0]), "+f"(c[1]), "+f"(c[2]), "+f"(c[3])
        : "r"(a[0]), "r"(a[1]), "r"(a[2]), "r"(a[3]), "r"(b[0]), "r"(b[1]));
}
__device__ __forceinline__ void ldsm4(uint32_t r[4], uint32_t addr) {
    asm volatile("ldmatrix.sync.aligned.m8n8.x4.shared.b16 {%0,%1,%2,%3}, [%4];"
        : "=r"(r[0]), "=r"(r[1]), "=r"(r[2]), "=r"(r[3]) : "r"(addr));
}

// ---------------- prep: classify + all bf16 conversions ----------------------
__global__ void prep_kernel(const float* __restrict__ i0, const float* __restrict__ i1,
                            const float* __restrict__ i2, const float* __restrict__ i3,
                            const float* __restrict__ lin0, const float* __restrict__ lin1,
                            const int* __restrict__ targets) {
    int t = blockIdx.x * blockDim.x + threadIdx.x;
    int gs = gridDim.x * blockDim.x;
    for (int i = t; i < NROWS; i += gs) {
        int tg = targets[i];
        if (tg >= CUT0 && tg < CUT1) { int p = atomicAdd(&g_cnt0, 1); g_idx0[p] = i; }
        else if (tg >= CUT1)         { int p = atomicAdd(&g_cnt1, 1); g_idx1[p] = i; }
    }
    const float* srcs[4] = { i0, i1, i2, i3 };
    __nv_bfloat16* dsts[4] = { g_inh, g_headWh, g_emb0h, g_emb1h };
    const int n4s[4] = { NROWS * KDIM / 4, NHEAD * KDIM / 4, SZ0 * D0 / 4, SZ1 * D1 / 4 };
    #pragma unroll
    for (int a = 0; a < 4; a++) {
        const float4* s = (const float4*)srcs[a];
        __nv_bfloat162* d = (__nv_bfloat162*)dsts[a];
        for (int i = t; i < n4s[a]; i += gs) {
            float4 v = s[i];
            d[2 * i]     = __floats2bfloat162_rn(v.x, v.y);
            d[2 * i + 1] = __floats2bfloat162_rn(v.z, v.w);
        }
    }
    for (int i = t; i < D0 * KDIM; i += gs) {
        int n = i >> 10, k = i & (KDIM - 1);
        g_lin0t[i] = __float2bfloat16(lin0[k * D0 + n]);
    }
    for (int i = t; i < D1 * KDIM; i += gs) {
        int n = i >> 10, k = i & (KDIM - 1);
        g_lin1t[i] = __float2bfloat16(lin1[k * D1 + n]);
    }
}

// ---------------- tensor-core projection (merged, 128-row tiles) -------------
template<int NOUT, int NBLK, int WHICH>
__device__ __forceinline__ void proj_body(uint32_t* sm, int yIdx) {
    const int AST = 20;
    const int NJ = NBLK / 16;
    uint32_t smB = (uint32_t)__cvta_generic_to_shared(sm);
    const uint32_t aOff[2] = { 0u, 2560u * 4 };
    const uint32_t bOff[2] = { 5120u * 4, (5120u + NBLK * AST) * 4 };

    float* __restrict__ P = (WHICH == 0) ? g_proj0 : g_proj1;
    __nv_bfloat16* __restrict__ Ph = (WHICH == 0) ? g_proj0h : g_proj1h;
    const __nv_bfloat16* __restrict__ Bt = (WHICH == 0) ? g_lin0t : g_lin1t;

    int tid = threadIdx.x;
    int row0 = blockIdx.x * 128;
    int nc = yIdx * NBLK;
    int warp = tid >> 5, lane = tid & 31, grp = lane >> 2, qid = lane & 3;
    int wm = (warp >> 1) * 32, wn = (warp & 1) * (NBLK / 2);

    int ar = tid >> 1, aSeg = (tid & 1) * 32;
    const char* aG = (const char*)(g_inh + (size_t)(row0 + ar) * KDIM) + aSeg;
    const int TPR = 256 / NBLK;
    const int SEG = 64 / TPR;
    int bRow = tid / TPR, bSeg = (tid % TPR) * SEG;
    const char* bG = (const char*)(Bt + (size_t)(nc + bRow) * KDIM) + bSeg;

    uint32_t aLd = (uint32_t)((wm + (lane & 15)) * AST + (lane >> 4) * 4) * 4;
    uint32_t bLd = (uint32_t)((wn + ((lane >> 4) & 1) * 8 + (lane & 7)) * AST
                              + ((lane >> 3) & 1) * 4) * 4;

    float c[2][NJ][4];
    #pragma unroll
    for (int mi = 0; mi < 2; mi++)
        #pragma unroll
        for (int nj = 0; nj < NJ; nj++)
            #pragma unroll
            for (int r = 0; r < 4; r++) c[mi][nj][r] = 0.f;

    {
        uint32_t as = smB + aOff[0] + (uint32_t)(ar * AST) * 4 + aSeg;
        cp16(as, aG, true); cp16(as + 16, aG + 16, true);
        uint32_t bs = smB + bOff[0] + (uint32_t)(bRow * AST) * 4 + bSeg;
        #pragma unroll
        for (int s = 0; s < SEG / 16; s++) cp16(bs + s * 16, bG + s * 16, true);
        cpcommit();
    }
    const int NCH = KDIM / 32;
    for (int ch = 0; ch < NCH; ch++) {
        int cur = ch & 1;
        if (ch + 1 < NCH) {
            int nb = cur ^ 1;
            uint32_t as = smB + aOff[nb] + (uint32_t)(ar * AST) * 4 + aSeg;
            const char* ag = aG + (ch + 1) * 64;
            cp16(as, ag, true); cp16(as + 16, ag + 16, true);
            uint32_t bs = smB + bOff[nb] + (uint32_t)(bRow * AST) * 4 + bSeg;
            const char* bg = bG + (ch + 1) * 64;
            #pragma unroll
            for (int s = 0; s < SEG / 16; s++) cp16(bs + s * 16, bg + s * 16, true);
            cpcommit(); cpwait<1>();
        } else cpwait<0>();
        __syncthreads();
        uint32_t aT = smB + aOff[cur] + aLd;
        uint32_t bT = smB + bOff[cur] + bLd;
        #pragma unroll
        for (int ks = 0; ks < 2; ks++) {
            uint32_t a[2][4], b[NJ][2];
            #pragma unroll
            for (int mi = 0; mi < 2; mi++)
                ldsm4(a[mi], aT + (uint32_t)(mi * 16 * AST + ks * 8) * 4);
            #pragma unroll
            for (int p = 0; p < NJ / 2; p++) {
                uint32_t r[4];
                ldsm4(r, bT + (uint32_t)(p * 16 * AST + ks * 8) * 4);
                b[2 * p][0] = r[0]; b[2 * p][1] = r[1];
                b[2 * p + 1][0] = r[2]; b[2 * p + 1][1] = r[3];
            }
            #pragma unroll
            for (int mi = 0; mi < 2; mi++)
                #pragma unroll
                for (int nj = 0; nj < NJ; nj++)
                    mma_bf16(c[mi][nj], a[mi], b[nj]);
        }
        __syncthreads();
    }
    #pragma unroll
    for (int mi = 0; mi < 2; mi++) {
        #pragma unroll
        for (int nj = 0; nj < NJ; nj++) {
            int r0 = row0 + wm + mi * 16 + grp;
            int col = nc + wn + nj * 8 + 2 * qid;
            long o0 = (long)r0 * NOUT + col;
            long o1 = (long)(r0 + 8) * NOUT + col;
            *reinterpret_cast<float2*>(&P[o0]) = make_float2(c[mi][nj][0], c[mi][nj][1]);
            *reinterpret_cast<float2*>(&P[o1]) = make_float2(c[mi][nj][2], c[mi][nj][3]);
            *reinterpret_cast<__nv_bfloat162*>(&Ph[o0]) =
                __floats2bfloat162_rn(c[mi][nj][0], c[mi][nj][1]);
            *reinterpret_cast<__nv_bfloat162*>(&Ph[o1]) =
                __floats2bfloat162_rn(c[mi][nj][2], c[mi][nj][3]);
        }
    }
}

__global__ void __launch_bounds__(256) proj_all() {
    extern __shared__ uint32_t smp[];
    if (blockIdx.y < 2) proj_body<D0, 128, 0>(smp, blockIdx.y);
    else                proj_body<D1, 64, 1>(smp, 0);
}

// =============== merged bf16 exp-sum, warp tile m64n32, 2 CTA/SM =============
// chunked (CH=64, ST=36): A[2][256*36=9216] | B[2][64*36=2304] @18432 | rowAcc @23040
// resident tail1:          A[256*36=9216]    | B[2][64*36]      @9216  | rowAcc @13824
#define SM_EXP_U32 23552

// ---- chunked body (head MODE 0 / tail0 MODE 1); N-tile 64, k-chunk 64 -------
template<int K, int MODE>
__device__ __forceinline__ void chunked_body(uint32_t* sm, int yIdx) {
    const int ST = 36;
    float* rowAcc = (float*)(sm + 23040);
    uint32_t smB = (uint32_t)__cvta_generic_to_shared(sm);
    const uint32_t aOff[2] = { 0u, 9216u * 4 };
    const uint32_t bOff[2] = { 18432u * 4, 20736u * 4 };

    int M, ncols;
    const __nv_bfloat16 *Asrc, *Bsrc;
    float* sums;
    if (MODE == 0) { M = NROWS; ncols = NHEAD; Asrc = g_inh;    Bsrc = g_headWh; sums = g_sum_head; }
    else           { M = g_cnt0; ncols = SZ0;  Asrc = g_proj0h; Bsrc = g_emb0h;  sums = g_sum_tail; }

    int row0 = blockIdx.x * 256;
    if (row0 >= M) return;
    int tid = threadIdx.x;
    int rid = row0 + tid; if (rid > M - 1) rid = M - 1;
    int myRow = (MODE == 0) ? rid : g_idx0[rid];
    rowAcc[tid] = 0.f;

    int warp = tid >> 5, lane = tid & 31, grp = lane >> 2, qid = lane & 3;
    int wm = (warp >> 1) * 64, wn = (warp & 1) * 32;
    int nc = yIdx * 64;

    // A: 1 thread per row, 128B (8 cp16) per chunk
    const char* aG = (const char*)(Asrc + (size_t)myRow * K);
    // B: 4 threads per row, 32B (2 cp16) each per chunk
    int bRow = tid >> 2, bSeg = (tid & 3) * 32;
    int bGRow = nc + bRow;
    bool bv = bGRow < ncols;
    const char* bG = (const char*)(Bsrc + (size_t)(bv ? bGRow : 0) * K);

    uint32_t aLd = (uint32_t)((wm + (lane & 15)) * ST + (lane >> 4) * 4) * 4;
    uint32_t bLd = (uint32_t)((wn + ((lane >> 4) & 1) * 8 + (lane & 7)) * ST
                              + ((lane >> 3) & 1) * 4) * 4;

    float c[4][4][4];
    #pragma unroll
    for (int mi = 0; mi < 4; mi++)
        #pragma unroll
        for (int nj = 0; nj < 4; nj++)
            #pragma unroll
            for (int r = 0; r < 4; r++) c[mi][nj][r] = 0.f;

    {   // chunk 0
        uint32_t as = smB + aOff[0] + (uint32_t)tid * ST * 4;
        #pragma unroll
        for (int s = 0; s < 8; s++) cp16(as + s * 16, aG + s * 16, true);
        uint32_t bs = smB + bOff[0] + (uint32_t)bRow * ST * 4 + bSeg;
        cp16(bs, bG + bSeg, bv); cp16(bs + 16, bG + bSeg + 16, bv);
        cpcommit();
    }
    const int NCH = K / 64;
    for (int ch = 0; ch < NCH; ch++) {
        int cur = ch & 1;
        if (ch + 1 < NCH) {
            int nb = cur ^ 1;
            uint32_t as = smB + aOff[nb] + (uint32_t)tid * ST * 4;
            const char* ag = aG + (ch + 1) * 128;
            #pragma unroll
            for (int s = 0; s < 8; s++) cp16(as + s * 16, ag + s * 16, true);
            uint32_t bs = smB + bOff[nb] + (uint32_t)bRow * ST * 4 + bSeg;
            const char* bg = bG + (ch + 1) * 128 + bSeg;
            cp16(bs, bg, bv); cp16(bs + 16, bg + 16, bv);
            cpcommit(); cpwait<1>();
        } else cpwait<0>();
        __syncthreads();
        uint32_t aT = smB + aOff[cur] + aLd;
        uint32_t bT = smB + bOff[cur] + bLd;
        #pragma unroll
        for (int ks = 0; ks < 4; ks++) {
            uint32_t a[4][4], b[4][2];
            #pragma unroll
            for (int mi = 0; mi < 4; mi++)
                ldsm4(a[mi], aT + (uint32_t)(mi * 16 * ST + ks * 8) * 4);
            #pragma unroll
            for (int p = 0; p < 2; p++) {
                uint32_t r[4];
                ldsm4(r, bT + (uint32_t)(p * 16 * ST + ks * 8) * 4);
                b[2 * p][0] = r[0]; b[2 * p][1] = r[1];
                b[2 * p + 1][0] = r[2]; b[2 * p + 1][1] = r[3];
            }
            #pragma unroll
            for (int mi = 0; mi < 4; mi++)
                #pragma unroll
                for (int nj = 0; nj < 4; nj++)
                    mma_bf16(c[mi][nj], a[mi], b[nj]);
        }
        __syncthreads();
    }
    #pragma unroll
    for (int mi = 0; mi < 4; mi++) {
        float s0 = 0.f, s1 = 0.f;
        #pragma unroll
        for (int nj = 0; nj < 4; nj++) {
            int col = nc + wn + nj * 8 + 2 * qid;
            if (col < ncols)     { s0 += __expf(c[mi][nj][0]); s1 += __expf(c[mi][nj][2]); }
            if (col + 1 < ncols) { s0 += __expf(c[mi][nj][1]); s1 += __expf(c[mi][nj][3]); }
        }
        s0 += __shfl_xor_sync(0xffffffffu, s0, 1);
        s0 += __shfl_xor_sync(0xffffffffu, s0, 2);
        s1 += __shfl_xor_sync(0xffffffffu, s1, 1);
        s1 += __shfl_xor_sync(0xffffffffu, s1, 2);
        if (qid == 0) {
            atomicAdd(&rowAcc[wm + mi * 16 + grp], s0);
            atomicAdd(&rowAcc[wm + mi * 16 + grp + 8], s1);
        }
    }
    __syncthreads();
    if (row0 + tid < M) atomicAdd(&sums[myRow], rowAcc[tid]);
}

// ---- tail1 resident body: K=64, A in smem once, B tiles double-buffered -----
template<int NUMY>
__device__ __forceinline__ void tail1_body(uint32_t* sm, int yIdx) {
    const int K = 64, ST = 36;
    float* rowAcc = (float*)(sm + 9216 + 4608);
    uint32_t smB = (uint32_t)__cvta_generic_to_shared(sm);
    const uint32_t bOff[2] = { 9216u * 4, (9216u + 2304u) * 4 };

    int M = g_cnt1;
    int ncols = SZ1;
    int row0 = blockIdx.x * 256;
    if (row0 >= M) return;
    int tid = threadIdx.x;
    int rid = row0 + tid; if (rid > M - 1) rid = M - 1;
    int myRow = g_idx1[rid];
    rowAcc[tid] = 0.f;

    {
        const char* aG = (const char*)(g_proj1h + (size_t)myRow * K);
        uint32_t as = smB + (uint32_t)tid * ST * 4;
        #pragma unroll
        for (int s = 0; s < 8; s++) cp16(as + s * 16, aG + s * 16, true);
    }
    int bRow = tid >> 2, bSeg = (tid & 3) * 32;
    int warp = tid >> 5, lane = tid & 31, grp = lane >> 2, qid = lane & 3;
    int wm = (warp >> 1) * 64, wn = (warp & 1) * 32;

    uint32_t aLd = (uint32_t)((wm + (lane & 15)) * ST + (lane >> 4) * 4) * 4;
    uint32_t bLd = (uint32_t)((wn + ((lane >> 4) & 1) * 8 + (lane & 7)) * ST
                              + ((lane >> 3) & 1) * 4) * 4;

    int ncStride = NUMY * 64;
    int nc0 = yIdx * 64;

    auto loadB = [&](int nc, int buf) {
        int br = nc + bRow;
        bool v = br < ncols;
        const char* bg = (const char*)(g_emb1h + (size_t)(v ? br : 0) * K) + bSeg;
        uint32_t bs = smB + bOff[buf] + (uint32_t)bRow * ST * 4 + bSeg;
        cp16(bs, bg, v); cp16(bs + 16, bg + 16, v);
    };
    if (nc0 < ncols) loadB(nc0, 0);
    cpcommit();

    int buf = 0;
    for (int nc = nc0; nc < ncols; nc += ncStride) {
        if (nc + ncStride < ncols) { loadB(nc + ncStride, buf ^ 1); cpcommit(); cpwait<1>(); }
        else cpwait<0>();
        __syncthreads();

        float c[4][4][4];
        #pragma unroll
        for (int mi = 0; mi < 4; mi++)
            #pragma unroll
            for (int nj = 0; nj < 4; nj++)
                #pragma unroll
                for (int r = 0; r < 4; r++) c[mi][nj][r] = 0.f;

        uint32_t aT = smB + aLd;
        uint32_t bT = smB + bOff[buf] + bLd;
        #pragma unroll
        for (int ks = 0; ks < 4; ks++) {
            uint32_t a[4][4], b[4][2];
            #pragma unroll
            for (int mi = 0; mi < 4; mi++)
                ldsm4(a[mi], aT + (uint32_t)(mi * 16 * ST + ks * 8) * 4);
            #pragma unroll
            for (int p = 0; p < 2; p++) {
                uint32_t r[4];
                ldsm4(r, bT + (uint32_t)(p * 16 * ST + ks * 8) * 4);
                b[2 * p][0] = r[0]; b[2 * p][1] = r[1];
                b[2 * p + 1][0] = r[2]; b[2 * p + 1][1] = r[3];
            }
            #pragma unroll
            for (int mi = 0; mi < 4; mi++)
                #pragma unroll
                for (int nj = 0; nj < 4; nj++)
                    mma_bf16(c[mi][nj], a[mi], b[nj]);
        }
        #pragma unroll
        for (int mi = 0; mi < 4; mi++) {
            float s0 = 0.f, s1 = 0.f;
            #pragma unroll
            for (int nj = 0; nj < 4; nj++) {
                int col = nc + wn + nj * 8 + 2 * qid;
                if (col < ncols)     { s0 += __expf(c[mi][nj][0]); s1 += __expf(c[mi][nj][2]); }
                if (col + 1 < ncols) { s0 += __expf(c[mi][nj][1]); s1 += __expf(c[mi][nj][3]); }
            }
            s0 += __shfl_xor_sync(0xffffffffu, s0, 1);
            s0 += __shfl_xor_sync(0xffffffffu, s0, 2);
            s1 += __shfl_xor_sync(0xffffffffu, s1, 1);
            s1 += __shfl_xor_sync(0xffffffffu, s1, 2);
            if (qid == 0) {
                atomicAdd(&rowAcc[wm + mi * 16 + grp], s0);
                atomicAdd(&rowAcc[wm + mi * 16 + grp + 8], s1);
            }
        }
        __syncthreads();
        buf ^= 1;
    }
    if (row0 + tid < M) atomicAdd(&g_sum_tail[myRow], rowAcc[tid]);
}

// y-map: [0,32) head tiles | [32,72) tail1 partitions | [72,197) tail0 tiles
__global__ void __launch_bounds__(256, 2) expsum_all() {
    extern __shared__ uint32_t sm[];
    if (blockIdx.y < 32)      chunked_body<KDIM, 0>(sm, blockIdx.y);
    else if (blockIdx.y < 72) tail1_body<40>(sm, blockIdx.y - 32);
    else                      chunked_body<D0, 1>(sm, blockIdx.y - 72);
}

// ---------------- final gather ----------------------------------------------
__global__ void __launch_bounds__(256) final_kernel(
    const float* __restrict__ inputs, const int* __restrict__ targets,
    const float* __restrict__ head_W, const float* __restrict__ emb0,
    const float* __restrict__ emb1, float* __restrict__ out)
{
    int warp = (blockIdx.x * blockDim.x + threadIdx.x) >> 5;
    int lane = threadIdx.x & 31;
    if (warp >= NROWS) return;
    int row = warp;
    int t = targets[row];
    int ht = (t < CUT0) ? t : ((t < CUT1) ? CUT0 : CUT0 + 1);

    float s = 0.f;
    const float* x = inputs + (long)row * KDIM;
    const float* w = head_W + (long)ht * KDIM;
    for (int k = lane; k < KDIM; k += 32) s += x[k] * w[k];
    #pragma unroll
    for (int o = 16; o; o >>= 1) s += __shfl_xor_sync(0xffffffffu, s, o);
    float res = s - logf(g_sum_head[row]);

    if (t >= CUT0) {
        float tl = 0.f;
        if (t < CUT1) {
            const float* p = g_proj0 + (long)row * D0;
            const float* e = emb0 + (long)(t - CUT0) * D0;
            for (int k = lane; k < D0; k += 32) tl += p[k] * e[k];
        } else {
            const float* p = g_proj1 + (long)row * D1;
            const float* e = emb1 + (long)(t - CUT1) * D1;
            for (int k = lane; k < D1; k += 32) tl += p[k] * e[k];
        }
        #pragma unroll
        for (int o = 16; o; o >>= 1) tl += __shfl_xor_sync(0xffffffffu, tl, o);
        res += tl - logf(g_sum_tail[row]);
    }
    if (lane == 0) out[row] = res;
}

// -------- loss reduction (double) + state reset for next replay ---------------
__global__ void __launch_bounds__(1024) loss_kernel(float* __restrict__ out, int out_size) {
    __shared__ double sh[1024];
    int tid = threadIdx.x;
    double s = 0.0;
    for (int i = tid; i < NROWS; i += 1024) s += (double)out[i];
    sh[tid] = s;
    __syncthreads();
    for (int o = 512; o; o >>= 1) {
        if (tid < o) sh[tid] += sh[tid + o];
        __syncthreads();
    }
    if (tid == 0 && out_size > NROWS)
        out[out_size - 1] = (float)(-sh[0] / (double)NROWS);
    for (int i = tid; i < NROWS; i += 1024) { g_sum_head[i] = 0.f; g_sum_tail[i] = 0.f; }
    if (tid == 0) { g_cnt0 = 0; g_cnt1 = 0; }
}

// ---------------- launch -----------------------------------------------------
extern "C" void kernel_launch(void* const* d_in, const int* in_sizes, int n_in,
                              void* d_out, int out_size) {
    const float* inputs = 0; const int* targets = 0; const float* head_W = 0;
    const float* emb0 = 0; const float* lin0 = 0; const float* emb1 = 0; const float* lin1 = 0;
    for (int i = 0; i < n_in; i++) {
        switch (in_sizes[i]) {
            case NROWS * KDIM:  inputs  = (const float*)d_in[i]; break;
            case NROWS:         targets = (const int*)  d_in[i]; break;
            case NHEAD * KDIM:  head_W  = (const float*)d_in[i]; break;
            case SZ0 * D0:      emb0    = (const float*)d_in[i]; break;
            case KDIM * D0:     lin0    = (const float*)d_in[i]; break;
            case SZ1 * D1:      emb1    = (const float*)d_in[i]; break;
            case KDIM * D1:     lin1    = (const float*)d_in[i]; break;
        }
    }
    float* out = (float*)d_out;

    const int SMEM_PROJ = (2 * 2560 + 2 * 128 * 20) * 4;    // 40 KB
    const int SMEM_EXP  = SM_EXP_U32 * 4;                   // 94.2 KB (2 CTA/SM)
    cudaFuncSetAttribute(proj_all,   cudaFuncAttributeMaxDynamicSharedMemorySize, SMEM_PROJ);
    cudaFuncSetAttribute(expsum_all, cudaFuncAttributeMaxDynamicSharedMemorySize, SMEM_EXP);

    prep_kernel<<<2048, 256>>>(inputs, head_W, emb0, emb1, lin0, lin1, targets);
    proj_all<<<dim3(32, 3), 256, SMEM_PROJ>>>();
    expsum_all<<<dim3(16, 197), 256, SMEM_EXP>>>();
    final_kernel<<<(NROWS * 32) / 256, 256>>>(inputs, targets, head_W, emb0, emb1, out);
    loss_kernel<<<1, 1024>>>(out, out_size);
}